// round 1
// baseline (speedup 1.0000x reference)
#include <cuda_runtime.h>
#include <math.h>

#define BATCH 8
#define CDIM  256
#define TCDIM 512
#define NPIX  2304          // 48*48
#define EPSN  1e-6f
#define SCALE 0.0625f       // 1/sqrt(256)

// ---------------- scratch (device globals: allocation-free) ----------------
__device__ float g_q[BATCH * NPIX * CDIM];                 // [B][N][C] normalized q
__device__ float g_k[BATCH * NPIX * CDIM];                 // [B][N][C] normalized k (k^T)
__device__ float g_v[BATCH * NPIX * CDIM];                 // [B][N][C] v^T
__device__ float g_S[(size_t)BATCH * NPIX * NPIX];         // [B][N][N] scores / probs
__device__ float g_o[BATCH * NPIX * CDIM];                 // [B][N][C] attention out

// ---------------------------------------------------------------------------
// proj: out[b][n][c] = sum_k in[b][k][n] * W[c][k]
// in: [BATCH, K, NPIX], W: [CDIM, K], out: [BATCH, NPIX, CDIM]
// 64x64 tile, BK=16, 256 threads, 4x4 per thread
// ---------------------------------------------------------------------------
__global__ void proj_kernel(const float* __restrict__ in, const float* __restrict__ W,
                            float* __restrict__ out, int K) {
    __shared__ float As[16][64];   // [kk][nn]
    __shared__ float Ws[16][65];   // [kk][cc], padded vs store conflicts
    const int b  = blockIdx.z;
    const int n0 = blockIdx.x * 64;
    const int c0 = blockIdx.y * 64;
    const int tid = threadIdx.x;
    const int tx = tid & 15, ty = tid >> 4;
    const float* inb = in + (size_t)b * K * NPIX;

    float acc[4][4] = {};
    for (int k0 = 0; k0 < K; k0 += 16) {
        #pragma unroll
        for (int e = tid; e < 16 * 64; e += 256) {
            int kk = e >> 6, nn = e & 63;
            As[kk][nn] = inb[(size_t)(k0 + kk) * NPIX + n0 + nn];
        }
        #pragma unroll
        for (int e = tid; e < 16 * 64; e += 256) {
            int kk = e & 15, cc = e >> 4;
            Ws[kk][cc] = W[(c0 + cc) * K + k0 + kk];
        }
        __syncthreads();
        #pragma unroll
        for (int kk = 0; kk < 16; kk++) {
            float a[4], w[4];
            #pragma unroll
            for (int i = 0; i < 4; i++) a[i] = As[kk][ty * 4 + i];
            #pragma unroll
            for (int j = 0; j < 4; j++) w[j] = Ws[kk][tx * 4 + j];
            #pragma unroll
            for (int i = 0; i < 4; i++)
                #pragma unroll
                for (int j = 0; j < 4; j++)
                    acc[i][j] += a[i] * w[j];
        }
        __syncthreads();
    }
    float* outb = out + (size_t)b * NPIX * CDIM;
    #pragma unroll
    for (int i = 0; i < 4; i++)
        #pragma unroll
        for (int j = 0; j < 4; j++)
            outb[(size_t)(n0 + ty * 4 + i) * CDIM + c0 + tx * 4 + j] = acc[i][j];
}

// ---------------------------------------------------------------------------
// normalize q and k rows (length CDIM=256) — one block per (b,n), 256 threads
// ---------------------------------------------------------------------------
__global__ void norm_kernel(float* __restrict__ q, float* __restrict__ k) {
    const size_t row = blockIdx.x;
    const int t = threadIdx.x;
    float* qr = q + row * CDIM;
    float* kr = k + row * CDIM;
    float qv = qr[t], kv = kr[t];
    float s1 = qv * qv, s2 = kv * kv;
    #pragma unroll
    for (int o = 16; o > 0; o >>= 1) {
        s1 += __shfl_xor_sync(0xffffffffu, s1, o);
        s2 += __shfl_xor_sync(0xffffffffu, s2, o);
    }
    __shared__ float sq[8], sk[8];
    if ((t & 31) == 0) { sq[t >> 5] = s1; sk[t >> 5] = s2; }
    __syncthreads();
    float tq = 0.f, tk = 0.f;
    #pragma unroll
    for (int i = 0; i < 8; i++) { tq += sq[i]; tk += sk[i]; }
    float rq = 1.0f / fmaxf(sqrtf(tq), EPSN);
    float rk = 1.0f / fmaxf(sqrtf(tk), EPSN);
    qr[t] = qv * rq;
    kr[t] = kv * rk;
}

// ---------------------------------------------------------------------------
// S[b][n][m] = SCALE * sum_c q[b][n][c] * k[b][m][c]   (A·B^T, both [N,C])
// ---------------------------------------------------------------------------
__global__ void s_kernel(const float* __restrict__ q, const float* __restrict__ k,
                         float* __restrict__ S) {
    __shared__ float Qs[64][17];
    __shared__ float Ks[64][17];
    const int b  = blockIdx.z;
    const int n0 = blockIdx.x * 64;
    const int m0 = blockIdx.y * 64;
    const int tid = threadIdx.x;
    const int tx = tid & 15, ty = tid >> 4;
    const float* qb = q + (size_t)b * NPIX * CDIM;
    const float* kb = k + (size_t)b * NPIX * CDIM;

    float acc[4][4] = {};
    for (int c0 = 0; c0 < CDIM; c0 += 16) {
        #pragma unroll
        for (int e = tid; e < 64 * 16; e += 256) {
            int rr = e >> 4, kk = e & 15;
            Qs[rr][kk] = qb[(size_t)(n0 + rr) * CDIM + c0 + kk];
            Ks[rr][kk] = kb[(size_t)(m0 + rr) * CDIM + c0 + kk];
        }
        __syncthreads();
        #pragma unroll
        for (int kk = 0; kk < 16; kk++) {
            float a[4], w[4];
            #pragma unroll
            for (int i = 0; i < 4; i++) a[i] = Qs[ty * 4 + i][kk];
            #pragma unroll
            for (int j = 0; j < 4; j++) w[j] = Ks[tx * 4 + j][kk];
            #pragma unroll
            for (int i = 0; i < 4; i++)
                #pragma unroll
                for (int j = 0; j < 4; j++)
                    acc[i][j] += a[i] * w[j];
        }
        __syncthreads();
    }
    float* Sb = S + (size_t)b * NPIX * NPIX;
    #pragma unroll
    for (int i = 0; i < 4; i++)
        #pragma unroll
        for (int j = 0; j < 4; j++)
            Sb[(size_t)(n0 + ty * 4 + i) * NPIX + m0 + tx * 4 + j] = acc[i][j] * SCALE;
}

// ---------------------------------------------------------------------------
// row softmax over NPIX — one block per (b,n) row, 256 threads, 9 elems each
// ---------------------------------------------------------------------------
__global__ void softmax_kernel(float* __restrict__ S) {
    float* r = S + (size_t)blockIdx.x * NPIX;
    const int t = threadIdx.x;
    __shared__ float red[8];

    float vmax = -3.4e38f;
    for (int i = t; i < NPIX; i += 256) vmax = fmaxf(vmax, r[i]);
    #pragma unroll
    for (int o = 16; o > 0; o >>= 1) vmax = fmaxf(vmax, __shfl_xor_sync(0xffffffffu, vmax, o));
    if ((t & 31) == 0) red[t >> 5] = vmax;
    __syncthreads();
    float m = red[0];
    #pragma unroll
    for (int i = 1; i < 8; i++) m = fmaxf(m, red[i]);
    __syncthreads();

    float s = 0.f;
    for (int i = t; i < NPIX; i += 256) {
        float e = __expf(r[i] - m);
        r[i] = e;
        s += e;
    }
    #pragma unroll
    for (int o = 16; o > 0; o >>= 1) s += __shfl_xor_sync(0xffffffffu, s, o);
    if ((t & 31) == 0) red[t >> 5] = s;
    __syncthreads();
    float tot = 0.f;
    #pragma unroll
    for (int i = 0; i < 8; i++) tot += red[i];
    float inv = 1.0f / tot;
    for (int i = t; i < NPIX; i += 256) r[i] *= inv;
}

// ---------------------------------------------------------------------------
// out[b][n][c] = sum_m P[b][n][m] * v[b][m][c]
// ---------------------------------------------------------------------------
__global__ void pv_kernel(const float* __restrict__ P, const float* __restrict__ v,
                          float* __restrict__ out) {
    __shared__ float Ps[64][17];   // [nn][kk]
    __shared__ float Vs[16][64];   // [kk][cc]
    const int b  = blockIdx.z;
    const int n0 = blockIdx.x * 64;
    const int c0 = blockIdx.y * 64;
    const int tid = threadIdx.x;
    const int tx = tid & 15, ty = tid >> 4;
    const float* Pb = P + (size_t)b * NPIX * NPIX;
    const float* vb = v + (size_t)b * NPIX * CDIM;

    float acc[4][4] = {};
    for (int m0 = 0; m0 < NPIX; m0 += 16) {
        #pragma unroll
        for (int e = tid; e < 64 * 16; e += 256) {
            int rr = e >> 4, kk = e & 15;
            Ps[rr][kk] = Pb[(size_t)(n0 + rr) * NPIX + m0 + kk];
        }
        #pragma unroll
        for (int e = tid; e < 16 * 64; e += 256) {
            int kk = e >> 6, cc = e & 63;
            Vs[kk][cc] = vb[(size_t)(m0 + kk) * CDIM + c0 + cc];
        }
        __syncthreads();
        #pragma unroll
        for (int kk = 0; kk < 16; kk++) {
            float a[4], w[4];
            #pragma unroll
            for (int i = 0; i < 4; i++) a[i] = Ps[ty * 4 + i][kk];
            #pragma unroll
            for (int j = 0; j < 4; j++) w[j] = Vs[kk][tx * 4 + j];
            #pragma unroll
            for (int i = 0; i < 4; i++)
                #pragma unroll
                for (int j = 0; j < 4; j++)
                    acc[i][j] += a[i] * w[j];
        }
        __syncthreads();
    }
    float* outb = out + (size_t)b * NPIX * CDIM;
    #pragma unroll
    for (int i = 0; i < 4; i++)
        #pragma unroll
        for (int j = 0; j < 4; j++)
            outb[(size_t)(n0 + ty * 4 + i) * CDIM + c0 + tx * 4 + j] = acc[i][j];
}

// ---------------------------------------------------------------------------
// y[b][c][n] = x[b][c][n] + alpha * o[b][n][c]  (transposed residual add)
// block (32,8), 32x32 tile per block
// ---------------------------------------------------------------------------
__global__ void final_kernel(const float* __restrict__ x, const float* __restrict__ o,
                             const float* __restrict__ alpha, float* __restrict__ y) {
    __shared__ float t[32][33];
    const int b  = blockIdx.z;
    const int n0 = blockIdx.x * 32;
    const int c0 = blockIdx.y * 32;
    const float a = *alpha;
    const float* ob = o + (size_t)b * NPIX * CDIM;
    #pragma unroll
    for (int i = 0; i < 4; i++) {
        int nn = threadIdx.y + i * 8;
        t[nn][threadIdx.x] = ob[(size_t)(n0 + nn) * CDIM + c0 + threadIdx.x];
    }
    __syncthreads();
    const float* xb = x + (size_t)b * CDIM * NPIX;
    float* yb = y + (size_t)b * CDIM * NPIX;
    #pragma unroll
    for (int i = 0; i < 4; i++) {
        int cc = threadIdx.y + i * 8;
        size_t idx = (size_t)(c0 + cc) * NPIX + n0 + threadIdx.x;
        yb[idx] = xb[idx] + a * t[threadIdx.x][cc];
    }
}

// ---------------------------------------------------------------------------
extern "C" void kernel_launch(void* const* d_in, const int* in_sizes, int n_in,
                              void* d_out, int out_size) {
    const float* x     = (const float*)d_in[0];
    const float* token = (const float*)d_in[1];
    const float* Wq    = (const float*)d_in[2];
    const float* Wk    = (const float*)d_in[3];
    const float* Wv    = (const float*)d_in[4];
    const float* alpha = (const float*)d_in[5];
    float* y = (float*)d_out;

    float *q, *k, *v, *S, *o;
    cudaGetSymbolAddress((void**)&q, g_q);
    cudaGetSymbolAddress((void**)&k, g_k);
    cudaGetSymbolAddress((void**)&v, g_v);
    cudaGetSymbolAddress((void**)&S, g_S);
    cudaGetSymbolAddress((void**)&o, g_o);

    dim3 gproj(NPIX / 64, CDIM / 64, BATCH);
    proj_kernel<<<gproj, 256>>>(x,     Wq, q, CDIM);
    proj_kernel<<<gproj, 256>>>(token, Wk, k, TCDIM);
    proj_kernel<<<gproj, 256>>>(token, Wv, v, TCDIM);

    norm_kernel<<<BATCH * NPIX, 256>>>(q, k);

    dim3 gs(NPIX / 64, NPIX / 64, BATCH);
    s_kernel<<<gs, 256>>>(q, k, S);

    softmax_kernel<<<BATCH * NPIX, 256>>>(S);

    pv_kernel<<<gproj, 256>>>(S, v, o);

    dim3 gf(NPIX / 32, CDIM / 32, BATCH);
    dim3 bf(32, 8);
    final_kernel<<<gf, bf>>>(x, o, alpha, y);
}

// round 6
// speedup vs baseline: 6.1448x; 6.1448x over previous
#include <cuda_runtime.h>
#include <cuda_bf16.h>
#include <math.h>
#include <cstdint>

#define BATCH 8
#define CDIM  256
#define TCDIM 512
#define NPIX  2304          // 48*48
#define EPSN  1e-6f
#define SCALE 0.0625f       // 1/sqrt(256)

// ---------------- scratch (device globals: allocation-free) ----------------
__device__ __nv_bfloat16 g_xT [BATCH * NPIX * CDIM];        // x^T bf16 [B][N][256]
__device__ __nv_bfloat16 g_tT [BATCH * NPIX * TCDIM];       // token^T bf16 [B][N][512]
__device__ __nv_bfloat16 g_Wqb[CDIM * CDIM];
__device__ __nv_bfloat16 g_Wkb[CDIM * TCDIM];
__device__ __nv_bfloat16 g_Wvb[CDIM * TCDIM];
__device__ float         g_qf [BATCH * NPIX * CDIM];        // q fp32 [N][C]
__device__ float         g_kf [BATCH * NPIX * CDIM];        // k fp32 [N][C]
__device__ float         g_vf [BATCH * NPIX * CDIM];        // v fp32 [N][C]
__device__ __nv_bfloat16 g_qb [BATCH * NPIX * CDIM];        // normalized q bf16
__device__ __nv_bfloat16 g_kb [BATCH * NPIX * CDIM];        // normalized k bf16
__device__ __nv_bfloat16 g_vT [BATCH * CDIM * NPIX];        // v^T bf16 [C][N]
__device__ float         g_S  [(size_t)BATCH * NPIX * NPIX];// scores fp32
__device__ __nv_bfloat16 g_P  [(size_t)BATCH * NPIX * NPIX];// probs bf16
__device__ float         g_o  [BATCH * NPIX * CDIM];        // attention out fp32 [N][C]

// ======================= PTX helpers =======================================
__device__ __forceinline__ uint32_t smem_u32(const void* p) {
    uint32_t a;
    asm("{ .reg .u64 t; cvta.to.shared.u64 t, %1; cvt.u32.u64 %0, t; }" : "=r"(a) : "l"(p));
    return a;
}
#define CP_ASYNC16(s, g) \
    asm volatile("cp.async.cg.shared.global [%0], [%1], 16;" :: "r"(s), "l"(g) : "memory")
#define CP_COMMIT()  asm volatile("cp.async.commit_group;" ::: "memory")
#define CP_WAIT1()   asm volatile("cp.async.wait_group 1;" ::: "memory")
#define CP_WAIT0()   asm volatile("cp.async.wait_group 0;" ::: "memory")
#define LDSM_X4(r0, r1, r2, r3, addr) \
    asm volatile("ldmatrix.sync.aligned.m8n8.x4.shared.b16 {%0,%1,%2,%3}, [%4];" \
        : "=r"(r0), "=r"(r1), "=r"(r2), "=r"(r3) : "r"(addr))
#define LDSM_X2(r0, r1, addr) \
    asm volatile("ldmatrix.sync.aligned.m8n8.x2.shared.b16 {%0,%1}, [%2];" \
        : "=r"(r0), "=r"(r1) : "r"(addr))
#define MMA16816(c, a, b) \
    asm volatile("mma.sync.aligned.m16n8k16.row.col.f32.bf16.bf16.f32 " \
        "{%0,%1,%2,%3}, {%4,%5,%6,%7}, {%8,%9}, {%0,%1,%2,%3};" \
        : "+f"((c)[0]), "+f"((c)[1]), "+f"((c)[2]), "+f"((c)[3]) \
        : "r"((a)[0]), "r"((a)[1]), "r"((a)[2]), "r"((a)[3]), "r"((b)[0]), "r"((b)[1]))

// ===========================================================================
// bf16 warp-MMA GEMM: D[128x128] = A(128,K) * B(128,K)^T, fp32 accum.
// 256 threads = 8 warps, each warp 64x32. K-chunks of 32, 2-stage cp.async.
// SMEM row stride = 40 bf16 (80B) to dodge ldmatrix bank conflicts.
// mode 0: out fp32;  mode 2: out fp32 * SCALE
// ===========================================================================
#define KCH     32
#define ROWB    80                         // bytes per smem row (32 bf16 + pad)
#define TILEB   (128 * ROWB)               // 10240 B per operand tile
#define STAGEB  (2 * TILEB)                // A + B per stage

__global__ void __launch_bounds__(256, 2)
gemm_bf16_kernel(const __nv_bfloat16* __restrict__ A, size_t sAb, int ldA,
                 const __nv_bfloat16* __restrict__ B, size_t sBb, int ldB,
                 int K, int mode, float* __restrict__ outF, size_t sOb, int ldO)
{
    __shared__ __align__(128) unsigned char smem[2 * STAGEB];   // 40960 B

    const int tid  = threadIdx.x;
    const int lane = tid & 31;
    const int wid  = tid >> 5;
    const int b  = blockIdx.z;
    const int m0 = blockIdx.x * 128;
    const int n0 = blockIdx.y * 128;
    const int wm = (wid >> 2) * 64;        // warp m offset
    const int wn = (wid & 3) * 32;         // warp n offset

    const uint32_t sbase = smem_u32(smem);
    const __nv_bfloat16* Ab = A + (size_t)b * sAb + (size_t)m0 * ldA;
    const __nv_bfloat16* Bb = B + (size_t)b * sBb + (size_t)n0 * ldB;

    // cp.async mapping: thread t loads row r = t>>1, 2 x 16B segments
    const int cr   = tid >> 1;
    const int cs   = tid & 1;              // segments cs and cs+2

    float acc[4][4][4];
    #pragma unroll
    for (int i = 0; i < 4; i++)
        #pragma unroll
        for (int j = 0; j < 4; j++)
            #pragma unroll
            for (int e = 0; e < 4; e++) acc[i][j][e] = 0.f;

    const int nch = K / KCH;

    // ---- async tile loader ----
    auto issue = [&](int ch, int buf) {
        const uint32_t sa = sbase + buf * STAGEB + cr * ROWB;
        const uint32_t sb = sa + TILEB;
        const __nv_bfloat16* ga = Ab + (size_t)cr * ldA + ch * KCH;
        const __nv_bfloat16* gb = Bb + (size_t)cr * ldB + ch * KCH;
        #pragma unroll
        for (int s = 0; s < 2; s++) {
            const int seg = cs + s * 2;
            CP_ASYNC16(sa + seg * 16, ga + seg * 8);
            CP_ASYNC16(sb + seg * 16, gb + seg * 8);
        }
    };

    issue(0, 0);
    CP_COMMIT();

    for (int ch = 0; ch < nch; ch++) {
        if (ch + 1 < nch) { issue(ch + 1, (ch + 1) & 1); CP_COMMIT(); CP_WAIT1(); }
        else              { CP_WAIT0(); }
        __syncthreads();

        const uint32_t aT = sbase + (ch & 1) * STAGEB;
        const uint32_t bT = aT + TILEB;
        #pragma unroll
        for (int ks = 0; ks < 2; ks++) {
            uint32_t af[4][4], bf[4][2];
            const int akoff = (ks * 16 + (lane >> 4) * 8) * 2;
            const int arow  = wm + (lane & 15);
            #pragma unroll
            for (int i = 0; i < 4; i++)
                LDSM_X4(af[i][0], af[i][1], af[i][2], af[i][3],
                        aT + (arow + i * 16) * ROWB + akoff);
            const int bkoff = (ks * 16 + ((lane >> 3) & 1) * 8) * 2;
            const int brow  = wn + (lane & 7);
            #pragma unroll
            for (int j = 0; j < 4; j++)
                LDSM_X2(bf[j][0], bf[j][1], bT + (brow + j * 8) * ROWB + bkoff);
            #pragma unroll
            for (int i = 0; i < 4; i++)
                #pragma unroll
                for (int j = 0; j < 4; j++)
                    MMA16816(acc[i][j], af[i], bf[j]);
        }
        __syncthreads();
    }

    // ---- epilogue: registers -> gmem, float2 stores ----
    const float sc = (mode == 2) ? SCALE : 1.0f;
    const int gid = lane >> 2, tig = lane & 3;
    float* outb = outF + (size_t)b * sOb;
    #pragma unroll
    for (int i = 0; i < 4; i++) {
        #pragma unroll
        for (int j = 0; j < 4; j++) {
            const int r0 = m0 + wm + i * 16 + gid;
            const int c  = n0 + wn + j * 8 + tig * 2;
            *reinterpret_cast<float2*>(outb + (size_t)r0 * ldO + c) =
                make_float2(acc[i][j][0] * sc, acc[i][j][1] * sc);
            *reinterpret_cast<float2*>(outb + (size_t)(r0 + 8) * ldO + c) =
                make_float2(acc[i][j][2] * sc, acc[i][j][3] * sc);
        }
    }
}

// ===========================================================================
// transpose + bf16 convert: out[b][n][k] = bf16(in[b][k][n])  (x/token prep)
// ===========================================================================
__global__ void trans_kernel(const float* __restrict__ in, __nv_bfloat16* __restrict__ out, int K) {
    __shared__ float t[32][33];
    const int b  = blockIdx.z;
    const int n0 = blockIdx.x * 32;
    const int k0 = blockIdx.y * 32;
    const float* ib = in + (size_t)b * K * NPIX;
    #pragma unroll
    for (int i = 0; i < 4; i++) {
        const int kk = threadIdx.y + i * 8;
        t[kk][threadIdx.x] = ib[(size_t)(k0 + kk) * NPIX + n0 + threadIdx.x];
    }
    __syncthreads();
    __nv_bfloat16* ob = out + (size_t)b * NPIX * K;
    #pragma unroll
    for (int i = 0; i < 4; i++) {
        const int nn = threadIdx.y + i * 8;
        ob[(size_t)(n0 + nn) * K + k0 + threadIdx.x] = __float2bfloat16(t[threadIdx.x][nn]);
    }
}

// v^T: out[b][c][n] = bf16(in[b][n][c])
__global__ void vt_kernel(const float* __restrict__ in, __nv_bfloat16* __restrict__ out) {
    __shared__ float t[32][33];
    const int b  = blockIdx.z;
    const int n0 = blockIdx.x * 32;
    const int c0 = blockIdx.y * 32;
    const float* ib = in + (size_t)b * NPIX * CDIM;
    #pragma unroll
    for (int i = 0; i < 4; i++) {
        const int nn = threadIdx.y + i * 8;
        t[nn][threadIdx.x] = ib[(size_t)(n0 + nn) * CDIM + c0 + threadIdx.x];
    }
    __syncthreads();
    __nv_bfloat16* ob = out + (size_t)b * CDIM * NPIX;
    #pragma unroll
    for (int i = 0; i < 4; i++) {
        const int cc = threadIdx.y + i * 8;
        ob[(size_t)(c0 + cc) * NPIX + n0 + threadIdx.x] = __float2bfloat16(t[threadIdx.x][cc]);
    }
}

__global__ void conv_bf16_kernel(const float* __restrict__ in, __nv_bfloat16* __restrict__ out, int n) {
    const int i = blockIdx.x * blockDim.x + threadIdx.x;
    if (i < n) out[i] = __float2bfloat16(in[i]);
}

// ===========================================================================
// normalize q,k rows (C=256); write bf16 — one block per (b,n)
// ===========================================================================
__global__ void norm_kernel(const float* __restrict__ q, const float* __restrict__ k,
                            __nv_bfloat16* __restrict__ qb, __nv_bfloat16* __restrict__ kb) {
    const size_t row = blockIdx.x;
    const int t = threadIdx.x;
    const float qv = q[row * CDIM + t];
    const float kv = k[row * CDIM + t];
    float s1 = qv * qv, s2 = kv * kv;
    #pragma unroll
    for (int o = 16; o > 0; o >>= 1) {
        s1 += __shfl_xor_sync(0xffffffffu, s1, o);
        s2 += __shfl_xor_sync(0xffffffffu, s2, o);
    }
    __shared__ float sq[8], sk[8];
    if ((t & 31) == 0) { sq[t >> 5] = s1; sk[t >> 5] = s2; }
    __syncthreads();
    float tq = 0.f, tk = 0.f;
    #pragma unroll
    for (int i = 0; i < 8; i++) { tq += sq[i]; tk += sk[i]; }
    const float rq = 1.0f / fmaxf(sqrtf(tq), EPSN);
    const float rk = 1.0f / fmaxf(sqrtf(tk), EPSN);
    qb[row * CDIM + t] = __float2bfloat16(qv * rq);
    kb[row * CDIM + t] = __float2bfloat16(kv * rk);
}

// ===========================================================================
// softmax: fp32 S row -> bf16 P row. 256 threads, 9 elems each in regs.
// ===========================================================================
__global__ void softmax_kernel(const float* __restrict__ S, __nv_bfloat16* __restrict__ P) {
    const size_t row = blockIdx.x;
    const int t = threadIdx.x;
    const float* r = S + row * NPIX;
    __nv_bfloat16* p = P + row * NPIX;
    float v[9];
    #pragma unroll
    for (int i = 0; i < 9; i++) v[i] = r[t + i * 256];

    __shared__ float red[8];
    float m = v[0];
    #pragma unroll
    for (int i = 1; i < 9; i++) m = fmaxf(m, v[i]);
    #pragma unroll
    for (int o = 16; o > 0; o >>= 1) m = fmaxf(m, __shfl_xor_sync(0xffffffffu, m, o));
    if ((t & 31) == 0) red[t >> 5] = m;
    __syncthreads();
    float mm = red[0];
    #pragma unroll
    for (int i = 1; i < 8; i++) mm = fmaxf(mm, red[i]);
    __syncthreads();

    float s = 0.f;
    #pragma unroll
    for (int i = 0; i < 9; i++) { v[i] = __expf(v[i] - mm); s += v[i]; }
    #pragma unroll
    for (int o = 16; o > 0; o >>= 1) s += __shfl_xor_sync(0xffffffffu, s, o);
    if ((t & 31) == 0) red[t >> 5] = s;
    __syncthreads();
    float tot = 0.f;
    #pragma unroll
    for (int i = 0; i < 8; i++) tot += red[i];
    const float inv = 1.0f / tot;
    #pragma unroll
    for (int i = 0; i < 9; i++) p[t + i * 256] = __float2bfloat16(v[i] * inv);
}

// ===========================================================================
// y[b][c][n] = x[b][c][n] + alpha * o[b][n][c]
// ===========================================================================
__global__ void final_kernel(const float* __restrict__ x, const float* __restrict__ o,
                             const float* __restrict__ alpha, float* __restrict__ y) {
    __shared__ float t[32][33];
    const int b  = blockIdx.z;
    const int n0 = blockIdx.x * 32;
    const int c0 = blockIdx.y * 32;
    const float a = *alpha;
    const float* ob = o + (size_t)b * NPIX * CDIM;
    #pragma unroll
    for (int i = 0; i < 4; i++) {
        const int nn = threadIdx.y + i * 8;
        t[nn][threadIdx.x] = ob[(size_t)(n0 + nn) * CDIM + c0 + threadIdx.x];
    }
    __syncthreads();
    const float* xb = x + (size_t)b * CDIM * NPIX;
    float* yb = y + (size_t)b * CDIM * NPIX;
    #pragma unroll
    for (int i = 0; i < 4; i++) {
        const int cc = threadIdx.y + i * 8;
        const size_t idx = (size_t)(c0 + cc) * NPIX + n0 + threadIdx.x;
        yb[idx] = xb[idx] + a * t[threadIdx.x][cc];
    }
}

// ===========================================================================
extern "C" void kernel_launch(void* const* d_in, const int* in_sizes, int n_in,
                              void* d_out, int out_size) {
    const float* x     = (const float*)d_in[0];
    const float* token = (const float*)d_in[1];
    const float* Wq    = (const float*)d_in[2];
    const float* Wk    = (const float*)d_in[3];
    const float* Wv    = (const float*)d_in[4];
    const float* alpha = (const float*)d_in[5];
    float* y = (float*)d_out;

    __nv_bfloat16 *xT, *tT, *Wqb, *Wkb, *Wvb, *qb, *kb, *vT, *P;
    float *qf, *kf, *vf, *S, *o;
    cudaGetSymbolAddress((void**)&xT,  g_xT);
    cudaGetSymbolAddress((void**)&tT,  g_tT);
    cudaGetSymbolAddress((void**)&Wqb, g_Wqb);
    cudaGetSymbolAddress((void**)&Wkb, g_Wkb);
    cudaGetSymbolAddress((void**)&Wvb, g_Wvb);
    cudaGetSymbolAddress((void**)&qf,  g_qf);
    cudaGetSymbolAddress((void**)&kf,  g_kf);
    cudaGetSymbolAddress((void**)&vf,  g_vf);
    cudaGetSymbolAddress((void**)&qb,  g_qb);
    cudaGetSymbolAddress((void**)&kb,  g_kb);
    cudaGetSymbolAddress((void**)&vT,  g_vT);
    cudaGetSymbolAddress((void**)&S,   g_S);
    cudaGetSymbolAddress((void**)&P,   g_P);
    cudaGetSymbolAddress((void**)&o,   g_o);

    // 1) weight converts + input transposes (fp32 -> bf16)
    conv_bf16_kernel<<<(CDIM * CDIM + 255) / 256, 256>>>(Wq, Wqb, CDIM * CDIM);
    conv_bf16_kernel<<<(CDIM * TCDIM + 255) / 256, 256>>>(Wk, Wkb, CDIM * TCDIM);
    conv_bf16_kernel<<<(CDIM * TCDIM + 255) / 256, 256>>>(Wv, Wvb, CDIM * TCDIM);
    {
        dim3 b1(32, 8);
        dim3 g1(NPIX / 32, CDIM / 32, BATCH);
        trans_kernel<<<g1, b1>>>(x, xT, CDIM);
        dim3 g2(NPIX / 32, TCDIM / 32, BATCH);
        trans_kernel<<<g2, b1>>>(token, tT, TCDIM);
    }

    // 2) projections on tensor cores (HMMA)
    dim3 gp(NPIX / 128, CDIM / 128, BATCH);   // 18 x 2 x 8
    gemm_bf16_kernel<<<gp, 256>>>(xT, (size_t)NPIX * CDIM, CDIM,
                                  Wqb, 0, CDIM,
                                  CDIM, 0,
                                  qf, (size_t)NPIX * CDIM, CDIM);
    gemm_bf16_kernel<<<gp, 256>>>(tT, (size_t)NPIX * TCDIM, TCDIM,
                                  Wkb, 0, TCDIM,
                                  TCDIM, 0,
                                  kf, (size_t)NPIX * CDIM, CDIM);
    gemm_bf16_kernel<<<gp, 256>>>(tT, (size_t)NPIX * TCDIM, TCDIM,
                                  Wvb, 0, TCDIM,
                                  TCDIM, 0,
                                  vf, (size_t)NPIX * CDIM, CDIM);

    // 3) normalize q,k -> bf16 ; transpose v -> bf16 [C][N]
    norm_kernel<<<BATCH * NPIX, 256>>>(qf, kf, qb, kb);
    {
        dim3 b1(32, 8);
        dim3 gv(NPIX / 32, CDIM / 32, BATCH);
        vt_kernel<<<gv, b1>>>(vf, vT);
    }

    // 4) S = (qn . kn^T) / 16   (K = CDIM, mode = 2)
    dim3 gs(NPIX / 128, NPIX / 128, BATCH);   // 18 x 18 x 8
    gemm_bf16_kernel<<<gs, 256>>>(qb, (size_t)NPIX * CDIM, CDIM,
                                  kb, (size_t)NPIX * CDIM, CDIM,
                                  CDIM, 2,
                                  S, (size_t)NPIX * NPIX, NPIX);

    // 5) softmax rows -> bf16 probs
    softmax_kernel<<<BATCH * NPIX, 256>>>(S, P);

    // 6) out = P . v   (A = P [N][N], B = vT [C][N], K = NPIX, mode = 0)
    gemm_bf16_kernel<<<gp, 256>>>(P, (size_t)NPIX * NPIX, NPIX,
                                  vT, (size_t)CDIM * NPIX, NPIX,
                                  NPIX, 0,
                                  o, (size_t)NPIX * CDIM, CDIM);

    // 7) residual add (transposed)
    dim3 gf(NPIX / 32, CDIM / 32, BATCH), bfb(32, 8);
    final_kernel<<<gf, bfb>>>(x, o, alpha, y);
}

// round 8
// speedup vs baseline: 8.4114x; 1.3689x over previous
#include <cuda_runtime.h>
#include <cuda_bf16.h>
#include <math.h>
#include <cstdint>

#define BATCH 8
#define CDIM  256
#define TCDIM 512
#define NPIX  2304          // 48*48
#define EPSN  1e-6f
#define SCALE 0.0625f       // 1/sqrt(256)

// ---------------- scratch (device globals: allocation-free) ----------------
__device__ __nv_bfloat16 g_xT [BATCH * NPIX * CDIM];        // x^T bf16 [B][N][256]
__device__ __nv_bfloat16 g_tT [BATCH * NPIX * TCDIM];       // token^T bf16 [B][N][512]
__device__ __nv_bfloat16 g_Wqb[CDIM * CDIM];
__device__ __nv_bfloat16 g_Wkb[CDIM * TCDIM];
__device__ __nv_bfloat16 g_Wvb[CDIM * TCDIM];
__device__ float         g_qf [BATCH * NPIX * CDIM];        // q fp32 [N][C]
__device__ float         g_kf [BATCH * NPIX * CDIM];        // k fp32 [N][C]
__device__ float         g_vf [BATCH * NPIX * CDIM];        // v fp32 [N][C]
__device__ __nv_bfloat16 g_qb [BATCH * NPIX * CDIM];        // normalized q bf16
__device__ __nv_bfloat16 g_kb [BATCH * NPIX * CDIM];        // normalized k bf16
__device__ __nv_bfloat16 g_vT [BATCH * CDIM * NPIX];        // v^T bf16 [C][N]
__device__ float         g_o  [BATCH * NPIX * CDIM];        // attention out fp32 [N][C]

// ======================= PTX helpers =======================================
__device__ __forceinline__ uint32_t smem_u32(const void* p) {
    uint32_t a;
    asm("{ .reg .u64 t; cvta.to.shared.u64 t, %1; cvt.u32.u64 %0, t; }" : "=r"(a) : "l"(p));
    return a;
}
__device__ __forceinline__ float ex2f(float x) {
    float y;
    asm("ex2.approx.f32 %0, %1;" : "=f"(y) : "f"(x));
    return y;
}
__device__ __forceinline__ uint32_t packbf(float lo, float hi) {
    __nv_bfloat162 h = __float22bfloat162_rn(make_float2(lo, hi));
    return *reinterpret_cast<uint32_t*>(&h);
}
#define CP_ASYNC16(s, g) \
    asm volatile("cp.async.cg.shared.global [%0], [%1], 16;" :: "r"(s), "l"(g) : "memory")
#define CP_COMMIT()  asm volatile("cp.async.commit_group;" ::: "memory")
#define CP_WAIT1()   asm volatile("cp.async.wait_group 1;" ::: "memory")
#define CP_WAIT0()   asm volatile("cp.async.wait_group 0;" ::: "memory")
#define LDSM_X4(r0, r1, r2, r3, addr) \
    asm volatile("ldmatrix.sync.aligned.m8n8.x4.shared.b16 {%0,%1,%2,%3}, [%4];" \
        : "=r"(r0), "=r"(r1), "=r"(r2), "=r"(r3) : "r"(addr))
#define LDSM_X2(r0, r1, addr) \
    asm volatile("ldmatrix.sync.aligned.m8n8.x2.shared.b16 {%0,%1}, [%2];" \
        : "=r"(r0), "=r"(r1) : "r"(addr))
#define MMA16816(c, a, b) \
    asm volatile("mma.sync.aligned.m16n8k16.row.col.f32.bf16.bf16.f32 " \
        "{%0,%1,%2,%3}, {%4,%5,%6,%7}, {%8,%9}, {%0,%1,%2,%3};" \
        : "+f"((c)[0]), "+f"((c)[1]), "+f"((c)[2]), "+f"((c)[3]) \
        : "r"((a)[0]), "r"((a)[1]), "r"((a)[2]), "r"((a)[3]), "r"((b)[0]), "r"((b)[1]))
#define MMA16816R(c, a0, a1, a2, a3, b0, b1) \
    asm volatile("mma.sync.aligned.m16n8k16.row.col.f32.bf16.bf16.f32 " \
        "{%0,%1,%2,%3}, {%4,%5,%6,%7}, {%8,%9}, {%0,%1,%2,%3};" \
        : "+f"((c)[0]), "+f"((c)[1]), "+f"((c)[2]), "+f"((c)[3]) \
        : "r"(a0), "r"(a1), "r"(a2), "r"(a3), "r"(b0), "r"(b1))

// ===========================================================================
// Fused attention: per CTA 128 q rows, full D=256 output.
// S = q.k^T (cosine sims, in [-1,1]); softmax with FIXED shift 1/16
// (logit = S/16 in [-1/16, 1/16] -> exact, no online max needed);
// O = sum(P.V) / sum(P).  k/v blocks of 64, double-buffered cp.async.
// ===========================================================================
#define BR    128
#define BC    64
#define NBLK  (NPIX / BC)                 // 36
#define QSTR  528                         // 256 bf16 + 16B pad
#define KSTR  528
#define VSTR  144                         // 64 bf16 + 16B pad
#define SM_K0   (BR * QSTR)               // 67584
#define SM_KB   (BC * KSTR)               // 33792
#define SM_V0   (SM_K0 + 2 * SM_KB)       // 135168
#define SM_VB   (CDIM * VSTR)             // 36864
#define SM_TOT  (SM_V0 + 2 * SM_VB)       // 208896

__global__ void __launch_bounds__(256, 1)
attn_kernel(const __nv_bfloat16* __restrict__ q,
            const __nv_bfloat16* __restrict__ k,
            const __nv_bfloat16* __restrict__ vT,
            float* __restrict__ out)
{
    extern __shared__ __align__(128) unsigned char smem[];
    const uint32_t sb = smem_u32(smem);

    const int tid  = threadIdx.x;
    const int lane = tid & 31;
    const int b    = blockIdx.y;
    const int m0   = blockIdx.x * BR;
    const int wrow = (tid >> 5) * 16;       // warp's q-row offset in tile
    const int gid  = lane >> 2, tig = lane & 3;

    const __nv_bfloat16* qg = q  + ((size_t)b * NPIX + m0) * CDIM;
    const __nv_bfloat16* kg = k  + (size_t)b * NPIX * CDIM;
    const __nv_bfloat16* vg = vT + (size_t)b * CDIM * NPIX;

    // ---- load q tile (once): 128 rows x 512B ----
    {
        const int row = tid >> 1, half = tid & 1;
        const uint32_t sq = sb + row * QSTR;
        const __nv_bfloat16* gq = qg + (size_t)row * CDIM;
        #pragma unroll
        for (int s = 0; s < 16; s++) {
            const int seg = half + 2 * s;
            CP_ASYNC16(sq + seg * 16, gq + seg * 8);
        }
    }

    // ---- k/v block loader ----
    auto loadKV = [&](int j, int buf) {
        {   // k block: 64 rows x 512B, 4 threads/row
            const int row = tid >> 2, q4 = tid & 3;
            const uint32_t sk = sb + SM_K0 + buf * SM_KB + row * KSTR;
            const __nv_bfloat16* gk = kg + (size_t)(j * BC + row) * CDIM;
            #pragma unroll
            for (int s = 0; s < 8; s++) {
                const int seg = q4 + 4 * s;
                CP_ASYNC16(sk + seg * 16, gk + seg * 8);
            }
        }
        {   // v block: 256 c-rows x 128B, 1 thread/row
            const uint32_t sv = sb + SM_V0 + buf * SM_VB + tid * VSTR;
            const __nv_bfloat16* gv = vg + (size_t)tid * NPIX + j * BC;
            #pragma unroll
            for (int s = 0; s < 8; s++)
                CP_ASYNC16(sv + s * 16, gv + s * 8);
        }
    };

    loadKV(0, 0);
    CP_COMMIT();
    CP_WAIT0();
    __syncthreads();

    float oacc[32][4];
    #pragma unroll
    for (int i = 0; i < 32; i++)
        #pragma unroll
        for (int e = 0; e < 4; e++) oacc[i][e] = 0.f;
    float l0 = 0.f, l1 = 0.f;

    const uint32_t sqa = sb + (wrow + (lane & 15)) * QSTR + (lane >> 4) * 16;
    const float C1 = SCALE * 1.44269504f;        // log2(e)/16
    const float C2 = SCALE * 1.44269504f;        // fixed shift 1/16 (scaled)

    for (int j = 0; j < NBLK; j++) {
        if (j + 1 < NBLK) { loadKV(j + 1, (j + 1) & 1); CP_COMMIT(); }

        // ---- S = q . k^T  (warp: 16 x 64, K = 256) ----
        float sacc[8][4];
        #pragma unroll
        for (int t = 0; t < 8; t++)
            #pragma unroll
            for (int e = 0; e < 4; e++) sacc[t][e] = 0.f;

        const uint32_t kTb = sb + SM_K0 + (j & 1) * SM_KB;
        const uint32_t kba = kTb + (lane & 7) * KSTR + ((lane >> 3) & 1) * 16;
        #pragma unroll
        for (int kc = 0; kc < 16; kc++) {
            uint32_t a[4];
            LDSM_X4(a[0], a[1], a[2], a[3], sqa + kc * 32);
            #pragma unroll
            for (int nt = 0; nt < 8; nt++) {
                uint32_t b0, b1;
                LDSM_X2(b0, b1, kba + nt * 8 * KSTR + kc * 32);
                MMA16816(sacc[nt], a, ((uint32_t[2]){b0, b1}));
            }
        }

        // ---- exp (fixed shift) + pack to bf16 A-fragments ----
        uint32_t pf[8][2];
        #pragma unroll
        for (int t = 0; t < 8; t++) {
            const float e0 = ex2f(fmaf(sacc[t][0], C1, -C2));
            const float e1 = ex2f(fmaf(sacc[t][1], C1, -C2));
            const float e2 = ex2f(fmaf(sacc[t][2], C1, -C2));
            const float e3 = ex2f(fmaf(sacc[t][3], C1, -C2));
            l0 += e0 + e1;
            l1 += e2 + e3;
            pf[t][0] = packbf(e0, e1);
            pf[t][1] = packbf(e2, e3);
        }

        // ---- O += P . V  (warp: 16 x 256, K = 64) ----
        const uint32_t vTb = sb + SM_V0 + (j & 1) * SM_VB;
        const uint32_t vba = vTb + (lane & 7) * VSTR + ((lane >> 3) & 1) * 16;
        #pragma unroll
        for (int kk = 0; kk < 4; kk++) {
            const uint32_t a0 = pf[2 * kk][0], a1 = pf[2 * kk][1];
            const uint32_t a2 = pf[2 * kk + 1][0], a3 = pf[2 * kk + 1][1];
            #pragma unroll
            for (int nt = 0; nt < 32; nt++) {
                uint32_t b0, b1;
                LDSM_X2(b0, b1, vba + nt * 8 * VSTR + kk * 32);
                MMA16816R(oacc[nt], a0, a1, a2, a3, b0, b1);
            }
        }

        CP_WAIT0();
        __syncthreads();
    }

    // ---- normalize rows and store ----
    l0 += __shfl_xor_sync(0xffffffffu, l0, 1);
    l0 += __shfl_xor_sync(0xffffffffu, l0, 2);
    l1 += __shfl_xor_sync(0xffffffffu, l1, 1);
    l1 += __shfl_xor_sync(0xffffffffu, l1, 2);
    const float inv0 = 1.0f / l0, inv1 = 1.0f / l1;

    float* og = out + (size_t)b * NPIX * CDIM;
    const int r0 = m0 + wrow + gid;
    #pragma unroll
    for (int nt = 0; nt < 32; nt++) {
        const int c = nt * 8 + tig * 2;
        *reinterpret_cast<float2*>(og + (size_t)r0 * CDIM + c) =
            make_float2(oacc[nt][0] * inv0, oacc[nt][1] * inv0);
        *reinterpret_cast<float2*>(og + (size_t)(r0 + 8) * CDIM + c) =
            make_float2(oacc[nt][2] * inv1, oacc[nt][3] * inv1);
    }
}

// ===========================================================================
// bf16 warp-MMA GEMM (projections): D[128x128] = A(128,K) * B(128,K)^T.
// ===========================================================================
#define KCH     32
#define ROWB    80
#define TILEB   (128 * ROWB)
#define STAGEB  (2 * TILEB)

__global__ void __launch_bounds__(256, 2)
gemm_bf16_kernel(const __nv_bfloat16* __restrict__ A, size_t sAb, int ldA,
                 const __nv_bfloat16* __restrict__ B, size_t sBb, int ldB,
                 int K, float* __restrict__ outF, size_t sOb, int ldO)
{
    __shared__ __align__(128) unsigned char smem[2 * STAGEB];

    const int tid  = threadIdx.x;
    const int lane = tid & 31;
    const int wid  = tid >> 5;
    const int b  = blockIdx.z;
    const int m0 = blockIdx.x * 128;
    const int n0 = blockIdx.y * 128;
    const int wm = (wid >> 2) * 64;
    const int wn = (wid & 3) * 32;

    const uint32_t sbase = smem_u32(smem);
    const __nv_bfloat16* Ab = A + (size_t)b * sAb + (size_t)m0 * ldA;
    const __nv_bfloat16* Bb = B + (size_t)b * sBb + (size_t)n0 * ldB;

    const int cr = tid >> 1;
    const int cs = tid & 1;

    float acc[4][4][4];
    #pragma unroll
    for (int i = 0; i < 4; i++)
        #pragma unroll
        for (int j = 0; j < 4; j++)
            #pragma unroll
            for (int e = 0; e < 4; e++) acc[i][j][e] = 0.f;

    const int nch = K / KCH;

    auto issue = [&](int ch, int buf) {
        const uint32_t sa = sbase + buf * STAGEB + cr * ROWB;
        const uint32_t sbm = sa + TILEB;
        const __nv_bfloat16* ga = Ab + (size_t)cr * ldA + ch * KCH;
        const __nv_bfloat16* gb = Bb + (size_t)cr * ldB + ch * KCH;
        #pragma unroll
        for (int s = 0; s < 2; s++) {
            const int seg = cs + s * 2;
            CP_ASYNC16(sa + seg * 16, ga + seg * 8);
            CP_ASYNC16(sbm + seg * 16, gb + seg * 8);
        }
    };

    issue(0, 0);
    CP_COMMIT();

    for (int ch = 0; ch < nch; ch++) {
        if (ch + 1 < nch) { issue(ch + 1, (ch + 1) & 1); CP_COMMIT(); CP_WAIT1(); }
        else              { CP_WAIT0(); }
        __syncthreads();

        const uint32_t aT = sbase + (ch & 1) * STAGEB;
        const uint32_t bT = aT + TILEB;
        #pragma unroll
        for (int ks = 0; ks < 2; ks++) {
            uint32_t af[4][4], bf[4][2];
            const int akoff = (ks * 16 + (lane >> 4) * 8) * 2;
            const int arow  = wm + (lane & 15);
            #pragma unroll
            for (int i = 0; i < 4; i++)
                LDSM_X4(af[i][0], af[i][1], af[i][2], af[i][3],
                        aT + (arow + i * 16) * ROWB + akoff);
            const int bkoff = (ks * 16 + ((lane >> 3) & 1) * 8) * 2;
            const int brow  = wn + (lane & 7);
            #pragma unroll
            for (int j = 0; j < 4; j++)
                LDSM_X2(bf[j][0], bf[j][1], bT + (brow + j * 8) * ROWB + bkoff);
            #pragma unroll
            for (int i = 0; i < 4; i++)
                #pragma unroll
                for (int j = 0; j < 4; j++)
                    MMA16816(acc[i][j], af[i], bf[j]);
        }
        __syncthreads();
    }

    const int gid = lane >> 2, tig = lane & 3;
    float* outb = outF + (size_t)b * sOb;
    #pragma unroll
    for (int i = 0; i < 4; i++) {
        #pragma unroll
        for (int j = 0; j < 4; j++) {
            const int r0 = m0 + wm + i * 16 + gid;
            const int c  = n0 + wn + j * 8 + tig * 2;
            *reinterpret_cast<float2*>(outb + (size_t)r0 * ldO + c) =
                make_float2(acc[i][j][0], acc[i][j][1]);
            *reinterpret_cast<float2*>(outb + (size_t)(r0 + 8) * ldO + c) =
                make_float2(acc[i][j][2], acc[i][j][3]);
        }
    }
}

// ===========================================================================
// transpose + bf16 convert: out[b][n][k] = bf16(in[b][k][n])
// ===========================================================================
__global__ void trans_kernel(const float* __restrict__ in, __nv_bfloat16* __restrict__ out, int K) {
    __shared__ float t[32][33];
    const int b  = blockIdx.z;
    const int n0 = blockIdx.x * 32;
    const int k0 = blockIdx.y * 32;
    const float* ib = in + (size_t)b * K * NPIX;
    #pragma unroll
    for (int i = 0; i < 4; i++) {
        const int kk = threadIdx.y + i * 8;
        t[kk][threadIdx.x] = ib[(size_t)(k0 + kk) * NPIX + n0 + threadIdx.x];
    }
    __syncthreads();
    __nv_bfloat16* ob = out + (size_t)b * NPIX * K;
    #pragma unroll
    for (int i = 0; i < 4; i++) {
        const int nn = threadIdx.y + i * 8;
        ob[(size_t)(n0 + nn) * K + k0 + threadIdx.x] = __float2bfloat16(t[threadIdx.x][nn]);
    }
}

// v^T: out[b][c][n] = bf16(in[b][n][c])
__global__ void vt_kernel(const float* __restrict__ in, __nv_bfloat16* __restrict__ out) {
    __shared__ float t[32][33];
    const int b  = blockIdx.z;
    const int n0 = blockIdx.x * 32;
    const int c0 = blockIdx.y * 32;
    const float* ib = in + (size_t)b * NPIX * CDIM;
    #pragma unroll
    for (int i = 0; i < 4; i++) {
        const int nn = threadIdx.y + i * 8;
        t[nn][threadIdx.x] = ib[(size_t)(n0 + nn) * CDIM + c0 + threadIdx.x];
    }
    __syncthreads();
    __nv_bfloat16* ob = out + (size_t)b * CDIM * NPIX;
    #pragma unroll
    for (int i = 0; i < 4; i++) {
        const int cc = threadIdx.y + i * 8;
        ob[(size_t)(c0 + cc) * NPIX + n0 + threadIdx.x] = __float2bfloat16(t[threadIdx.x][cc]);
    }
}

__global__ void conv_bf16_kernel(const float* __restrict__ in, __nv_bfloat16* __restrict__ out, int n) {
    const int i = blockIdx.x * blockDim.x + threadIdx.x;
    if (i < n) out[i] = __float2bfloat16(in[i]);
}

// ===========================================================================
// normalize q,k rows (C=256); write bf16 — one block per (b,n)
// ===========================================================================
__global__ void norm_kernel(const float* __restrict__ q, const float* __restrict__ k,
                            __nv_bfloat16* __restrict__ qb, __nv_bfloat16* __restrict__ kb) {
    const size_t row = blockIdx.x;
    const int t = threadIdx.x;
    const float qv = q[row * CDIM + t];
    const float kv = k[row * CDIM + t];
    float s1 = qv * qv, s2 = kv * kv;
    #pragma unroll
    for (int o = 16; o > 0; o >>= 1) {
        s1 += __shfl_xor_sync(0xffffffffu, s1, o);
        s2 += __shfl_xor_sync(0xffffffffu, s2, o);
    }
    __shared__ float sq[8], sk[8];
    if ((t & 31) == 0) { sq[t >> 5] = s1; sk[t >> 5] = s2; }
    __syncthreads();
    float tq = 0.f, tk = 0.f;
    #pragma unroll
    for (int i = 0; i < 8; i++) { tq += sq[i]; tk += sk[i]; }
    const float rq = 1.0f / fmaxf(sqrtf(tq), EPSN);
    const float rk = 1.0f / fmaxf(sqrtf(tk), EPSN);
    qb[row * CDIM + t] = __float2bfloat16(qv * rq);
    kb[row * CDIM + t] = __float2bfloat16(kv * rk);
}

// ===========================================================================
// y[b][c][n] = x[b][c][n] + alpha * o[b][n][c]
// ===========================================================================
__global__ void final_kernel(const float* __restrict__ x, const float* __restrict__ o,
                             const float* __restrict__ alpha, float* __restrict__ y) {
    __shared__ float t[32][33];
    const int b  = blockIdx.z;
    const int n0 = blockIdx.x * 32;
    const int c0 = blockIdx.y * 32;
    const float a = *alpha;
    const float* ob = o + (size_t)b * NPIX * CDIM;
    #pragma unroll
    for (int i = 0; i < 4; i++) {
        const int nn = threadIdx.y + i * 8;
        t[nn][threadIdx.x] = ob[(size_t)(n0 + nn) * CDIM + c0 + threadIdx.x];
    }
    __syncthreads();
    const float* xb = x + (size_t)b * CDIM * NPIX;
    float* yb = y + (size_t)b * CDIM * NPIX;
    #pragma unroll
    for (int i = 0; i < 4; i++) {
        const int cc = threadIdx.y + i * 8;
        const size_t idx = (size_t)(c0 + cc) * NPIX + n0 + threadIdx.x;
        yb[idx] = xb[idx] + a * t[threadIdx.x][cc];
    }
}

// ===========================================================================
extern "C" void kernel_launch(void* const* d_in, const int* in_sizes, int n_in,
                              void* d_out, int out_size) {
    const float* x     = (const float*)d_in[0];
    const float* token = (const float*)d_in[1];
    const float* Wq    = (const float*)d_in[2];
    const float* Wk    = (const float*)d_in[3];
    const float* Wv    = (const float*)d_in[4];
    const float* alpha = (const float*)d_in[5];
    float* y = (float*)d_out;

    __nv_bfloat16 *xT, *tT, *Wqb, *Wkb, *Wvb, *qb, *kb, *vT;
    float *qf, *kf, *vf, *o;
    cudaGetSymbolAddress((void**)&xT,  g_xT);
    cudaGetSymbolAddress((void**)&tT,  g_tT);
    cudaGetSymbolAddress((void**)&Wqb, g_Wqb);
    cudaGetSymbolAddress((void**)&Wkb, g_Wkb);
    cudaGetSymbolAddress((void**)&Wvb, g_Wvb);
    cudaGetSymbolAddress((void**)&qf,  g_qf);
    cudaGetSymbolAddress((void**)&kf,  g_kf);
    cudaGetSymbolAddress((void**)&vf,  g_vf);
    cudaGetSymbolAddress((void**)&qb,  g_qb);
    cudaGetSymbolAddress((void**)&kb,  g_kb);
    cudaGetSymbolAddress((void**)&vT,  g_vT);
    cudaGetSymbolAddress((void**)&o,   g_o);

    cudaFuncSetAttribute(attn_kernel, cudaFuncAttributeMaxDynamicSharedMemorySize, SM_TOT);

    // 1) weight converts + input transposes (fp32 -> bf16)
    conv_bf16_kernel<<<(CDIM * CDIM + 255) / 256, 256>>>(Wq, Wqb, CDIM * CDIM);
    conv_bf16_kernel<<<(CDIM * TCDIM + 255) / 256, 256>>>(Wk, Wkb, CDIM * TCDIM);
    conv_bf16_kernel<<<(CDIM * TCDIM + 255) / 256, 256>>>(Wv, Wvb, CDIM * TCDIM);
    {
        dim3 b1(32, 8);
        dim3 g1(NPIX / 32, CDIM / 32, BATCH);
        trans_kernel<<<g1, b1>>>(x, xT, CDIM);
        dim3 g2(NPIX / 32, TCDIM / 32, BATCH);
        trans_kernel<<<g2, b1>>>(token, tT, TCDIM);
    }

    // 2) projections on tensor cores (HMMA)
    dim3 gp(NPIX / 128, CDIM / 128, BATCH);   // 18 x 2 x 8
    gemm_bf16_kernel<<<gp, 256>>>(xT, (size_t)NPIX * CDIM, CDIM,
                                  Wqb, 0, CDIM, CDIM,
                                  qf, (size_t)NPIX * CDIM, CDIM);
    gemm_bf16_kernel<<<gp, 256>>>(tT, (size_t)NPIX * TCDIM, TCDIM,
                                  Wkb, 0, TCDIM, TCDIM,
                                  kf, (size_t)NPIX * CDIM, CDIM);
    gemm_bf16_kernel<<<gp, 256>>>(tT, (size_t)NPIX * TCDIM, TCDIM,
                                  Wvb, 0, TCDIM, TCDIM,
                                  vf, (size_t)NPIX * CDIM, CDIM);

    // 3) normalize q,k -> bf16 ; transpose v -> bf16 [C][N]
    norm_kernel<<<BATCH * NPIX, 256>>>(qf, kf, qb, kb);
    {
        dim3 b1(32, 8);
        dim3 gv(NPIX / 32, CDIM / 32, BATCH);
        vt_kernel<<<gv, b1>>>(vf, vT);
    }

    // 4) fused attention: S -> softmax(fixed shift) -> P.V -> o [N][C]
    dim3 ga(NPIX / BR, BATCH);                // 18 x 8 = 144 CTAs (one wave)
    attn_kernel<<<ga, 256, SM_TOT>>>(qb, kb, vT, o);

    // 5) residual add (transposed)
    dim3 gf(NPIX / 32, CDIM / 32, BATCH), bfb(32, 8);
    final_kernel<<<gf, bfb>>>(x, o, alpha, y);
}

// round 13
// speedup vs baseline: 9.2257x; 1.0968x over previous
#include <cuda_runtime.h>
#include <cuda_bf16.h>
#include <math.h>
#include <cstdint>

#define BATCH 8
#define CDIM  256
#define TCDIM 512
#define NPIX  2304          // 48*48
#define EPSN  1e-6f
#define SCALE 0.0625f       // 1/sqrt(256)

// ---------------- scratch (device globals: allocation-free) ----------------
__device__ __nv_bfloat16 g_xT [BATCH * NPIX * CDIM];        // x^T bf16 [B][N][256]
__device__ __nv_bfloat16 g_tT [BATCH * NPIX * TCDIM];       // token^T bf16 [B][N][512]
__device__ __nv_bfloat16 g_Wqb[CDIM * CDIM];
__device__ __nv_bfloat16 g_Wkb[CDIM * TCDIM];
__device__ __nv_bfloat16 g_Wvb[CDIM * TCDIM];
__device__ float         g_qf [BATCH * NPIX * CDIM];        // q fp32 [N][C]
__device__ float         g_kf [BATCH * NPIX * CDIM];        // k fp32 [N][C]
__device__ __nv_bfloat16 g_qb [BATCH * NPIX * CDIM];        // normalized q bf16
__device__ __nv_bfloat16 g_kb [BATCH * NPIX * CDIM];        // normalized k bf16
__device__ __nv_bfloat16 g_vT [BATCH * CDIM * NPIX];        // v^T bf16 [C][N]

// ======================= PTX helpers =======================================
__device__ __forceinline__ uint32_t smem_u32(const void* p) {
    uint32_t a;
    asm("{ .reg .u64 t; cvta.to.shared.u64 t, %1; cvt.u32.u64 %0, t; }" : "=r"(a) : "l"(p));
    return a;
}
__device__ __forceinline__ float ex2f(float x) {
    float y;
    asm("ex2.approx.f32 %0, %1;" : "=f"(y) : "f"(x));
    return y;
}
__device__ __forceinline__ uint32_t packbf(float lo, float hi) {
    __nv_bfloat162 h = __float22bfloat162_rn(make_float2(lo, hi));
    return *reinterpret_cast<uint32_t*>(&h);
}
#define CP_ASYNC16(s, g) \
    asm volatile("cp.async.cg.shared.global [%0], [%1], 16;" :: "r"(s), "l"(g) : "memory")
#define CP_COMMIT()  asm volatile("cp.async.commit_group;" ::: "memory")
#define CP_WAIT1()   asm volatile("cp.async.wait_group 1;" ::: "memory")
#define CP_WAIT0()   asm volatile("cp.async.wait_group 0;" ::: "memory")
#define LDSM_X4(r0, r1, r2, r3, addr) \
    asm volatile("ldmatrix.sync.aligned.m8n8.x4.shared.b16 {%0,%1,%2,%3}, [%4];" \
        : "=r"(r0), "=r"(r1), "=r"(r2), "=r"(r3) : "r"(addr))
#define LDSM_X2(r0, r1, addr) \
    asm volatile("ldmatrix.sync.aligned.m8n8.x2.shared.b16 {%0,%1}, [%2];" \
        : "=r"(r0), "=r"(r1) : "r"(addr))
#define MMA16816(c, a, b) \
    asm volatile("mma.sync.aligned.m16n8k16.row.col.f32.bf16.bf16.f32 " \
        "{%0,%1,%2,%3}, {%4,%5,%6,%7}, {%8,%9}, {%0,%1,%2,%3};" \
        : "+f"((c)[0]), "+f"((c)[1]), "+f"((c)[2]), "+f"((c)[3]) \
        : "r"((a)[0]), "r"((a)[1]), "r"((a)[2]), "r"((a)[3]), "r"((b)[0]), "r"((b)[1]))
#define MMA16816R(c, a0, a1, a2, a3, b0, b1) \
    asm volatile("mma.sync.aligned.m16n8k16.row.col.f32.bf16.bf16.f32 " \
        "{%0,%1,%2,%3}, {%4,%5,%6,%7}, {%8,%9}, {%0,%1,%2,%3};" \
        : "+f"((c)[0]), "+f"((c)[1]), "+f"((c)[2]), "+f"((c)[3]) \
        : "r"(a0), "r"(a1), "r"(a2), "r"(a3), "r"(b0), "r"(b1))

// ===========================================================================
// Fused attention + residual: per CTA 128 q rows, full D=256.
// Fixed-shift softmax (logits in [-1/16,1/16]); O = sum(P.V)/sum(P);
// epilogue stages O^T in smem and writes y = x + alpha*O^T coalesced.
// ===========================================================================
#define BR    128
#define BC    64
#define NBLK  (NPIX / BC)                 // 36
#define QSTR  528
#define KSTR  528
#define VSTR  144
#define SM_K0   (BR * QSTR)               // 67584
#define SM_KB   (BC * KSTR)               // 33792
#define SM_V0   (SM_K0 + 2 * SM_KB)       // 135168
#define SM_VB   (CDIM * VSTR)             // 36864
#define SM_TOT  (SM_V0 + 2 * SM_VB)       // 208896  (>= 256*136*4 = 139264)
#define OSTR  136

__global__ void __launch_bounds__(256, 1)
attn_kernel(const __nv_bfloat16* __restrict__ q,
            const __nv_bfloat16* __restrict__ k,
            const __nv_bfloat16* __restrict__ vT,
            const float* __restrict__ x,
            const float* __restrict__ alpha,
            float* __restrict__ y)
{
    extern __shared__ __align__(128) unsigned char smem[];
    const uint32_t sb = smem_u32(smem);

    const int tid  = threadIdx.x;
    const int lane = tid & 31;
    const int wid  = tid >> 5;
    const int b    = blockIdx.y;
    const int m0   = blockIdx.x * BR;
    const int wrow = wid * 16;
    const int gid  = lane >> 2, tig = lane & 3;

    const __nv_bfloat16* qg = q  + ((size_t)b * NPIX + m0) * CDIM;
    const __nv_bfloat16* kg = k  + (size_t)b * NPIX * CDIM;
    const __nv_bfloat16* vg = vT + (size_t)b * CDIM * NPIX;
    const float av = *alpha;

    // ---- load q tile (once) ----
    {
        const int row = tid >> 1, half = tid & 1;
        const uint32_t sq = sb + row * QSTR;
        const __nv_bfloat16* gq = qg + (size_t)row * CDIM;
        #pragma unroll
        for (int s = 0; s < 16; s++) {
            const int seg = half + 2 * s;
            CP_ASYNC16(sq + seg * 16, gq + seg * 8);
        }
    }

    auto loadKV = [&](int j, int buf) {
        {
            const int row = tid >> 2, q4 = tid & 3;
            const uint32_t sk = sb + SM_K0 + buf * SM_KB + row * KSTR;
            const __nv_bfloat16* gk = kg + (size_t)(j * BC + row) * CDIM;
            #pragma unroll
            for (int s = 0; s < 8; s++) {
                const int seg = q4 + 4 * s;
                CP_ASYNC16(sk + seg * 16, gk + seg * 8);
            }
        }
        {
            const uint32_t sv = sb + SM_V0 + buf * SM_VB + tid * VSTR;
            const __nv_bfloat16* gv = vg + (size_t)tid * NPIX + j * BC;
            #pragma unroll
            for (int s = 0; s < 8; s++)
                CP_ASYNC16(sv + s * 16, gv + s * 8);
        }
    };

    loadKV(0, 0);
    CP_COMMIT();
    CP_WAIT0();
    __syncthreads();

    float oacc[32][4];
    #pragma unroll
    for (int i = 0; i < 32; i++)
        #pragma unroll
        for (int e = 0; e < 4; e++) oacc[i][e] = 0.f;
    float l0 = 0.f, l1 = 0.f;

    const uint32_t sqa = sb + (wrow + (lane & 15)) * QSTR + (lane >> 4) * 16;
    const int x4row = (lane >> 4) * 8 + (lane & 7);
    const int x4off = ((lane >> 3) & 1) * 16;
    const float C1 = SCALE * 1.44269504f;
    const float C2 = SCALE * 1.44269504f;

    for (int j = 0; j < NBLK; j++) {
        if (j + 1 < NBLK) { loadKV(j + 1, (j + 1) & 1); CP_COMMIT(); }

        // ---- S = q . k^T ----
        float sacc[8][4];
        #pragma unroll
        for (int t = 0; t < 8; t++)
            #pragma unroll
            for (int e = 0; e < 4; e++) sacc[t][e] = 0.f;

        const uint32_t kba4 = sb + SM_K0 + (j & 1) * SM_KB + x4row * KSTR + x4off;
        #pragma unroll
        for (int kc = 0; kc < 16; kc++) {
            uint32_t a[4];
            LDSM_X4(a[0], a[1], a[2], a[3], sqa + kc * 32);
            #pragma unroll
            for (int np = 0; np < 4; np++) {
                uint32_t b0, b1, b2, b3;
                LDSM_X4(b0, b1, b2, b3, kba4 + np * 16 * KSTR + kc * 32);
                MMA16816R(sacc[2 * np],     a[0], a[1], a[2], a[3], b0, b1);
                MMA16816R(sacc[2 * np + 1], a[0], a[1], a[2], a[3], b2, b3);
            }
        }

        // ---- exp (fixed shift) + pack ----
        uint32_t pf[8][2];
        #pragma unroll
        for (int t = 0; t < 8; t++) {
            const float e0 = ex2f(fmaf(sacc[t][0], C1, -C2));
            const float e1 = ex2f(fmaf(sacc[t][1], C1, -C2));
            const float e2 = ex2f(fmaf(sacc[t][2], C1, -C2));
            const float e3 = ex2f(fmaf(sacc[t][3], C1, -C2));
            l0 += e0 + e1;
            l1 += e2 + e3;
            pf[t][0] = packbf(e0, e1);
            pf[t][1] = packbf(e2, e3);
        }

        // ---- O += P . V ----
        const uint32_t vba4 = sb + SM_V0 + (j & 1) * SM_VB + x4row * VSTR + x4off;
        #pragma unroll
        for (int kk = 0; kk < 4; kk++) {
            const uint32_t a0 = pf[2 * kk][0], a1 = pf[2 * kk][1];
            const uint32_t a2 = pf[2 * kk + 1][0], a3 = pf[2 * kk + 1][1];
            #pragma unroll
            for (int np = 0; np < 16; np++) {
                uint32_t b0, b1, b2, b3;
                LDSM_X4(b0, b1, b2, b3, vba4 + np * 16 * VSTR + kk * 32);
                MMA16816R(oacc[2 * np],     a0, a1, a2, a3, b0, b1);
                MMA16816R(oacc[2 * np + 1], a0, a1, a2, a3, b2, b3);
            }
        }

        CP_WAIT0();
        __syncthreads();
    }

    // ---- normalize, stage O^T in smem ----
    l0 += __shfl_xor_sync(0xffffffffu, l0, 1);
    l0 += __shfl_xor_sync(0xffffffffu, l0, 2);
    l1 += __shfl_xor_sync(0xffffffffu, l1, 1);
    l1 += __shfl_xor_sync(0xffffffffu, l1, 2);
    const float inv0 = 1.0f / l0, inv1 = 1.0f / l1;

    float* smO = reinterpret_cast<float*>(smem);   // [256 c][136 n]
    const int rl = wrow + gid;
    #pragma unroll
    for (int nt = 0; nt < 32; nt++) {
        const int c = nt * 8 + tig * 2;
        smO[c * OSTR + rl]           = oacc[nt][0] * inv0;
        smO[(c + 1) * OSTR + rl]     = oacc[nt][1] * inv0;
        smO[c * OSTR + rl + 8]       = oacc[nt][2] * inv1;
        smO[(c + 1) * OSTR + rl + 8] = oacc[nt][3] * inv1;
    }
    __syncthreads();

    // ---- y = x + alpha * O^T  (coalesced float4) ----
    const float* xg = x + (size_t)b * CDIM * NPIX + m0;
    float*       yg = y + (size_t)b * CDIM * NPIX + m0;
    #pragma unroll 4
    for (int t = 0; t < 32; t++) {
        const int cc = wid + t * 8;
        const float4 xv = *reinterpret_cast<const float4*>(xg + (size_t)cc * NPIX + lane * 4);
        const float4 ov = *reinterpret_cast<const float4*>(&smO[cc * OSTR + lane * 4]);
        float4 r;
        r.x = fmaf(av, ov.x, xv.x);
        r.y = fmaf(av, ov.y, xv.y);
        r.z = fmaf(av, ov.z, xv.z);
        r.w = fmaf(av, ov.w, xv.w);
        *reinterpret_cast<float4*>(yg + (size_t)cc * NPIX + lane * 4) = r;
    }
}

// ===========================================================================
// bf16 warp-MMA GEMM: D[128x128] = A(128,K) * B(128,K)^T.
// mode 0: fp32 out [m][n];  mode 1: bf16 transposed out [n][m] (via smem)
// ===========================================================================
#define KCH     32
#define ROWB    80
#define TILEB   (128 * ROWB)
#define STAGEB  (2 * TILEB)

__global__ void __launch_bounds__(256, 2)
gemm_bf16_kernel(const __nv_bfloat16* __restrict__ A, size_t sAb, int ldA,
                 const __nv_bfloat16* __restrict__ B, size_t sBb, int ldB,
                 int K, int mode,
                 float* __restrict__ outF, __nv_bfloat16* __restrict__ outBT,
                 size_t sOb, int ldO)
{
    __shared__ __align__(128) unsigned char smem[2 * STAGEB];

    const int tid  = threadIdx.x;
    const int lane = tid & 31;
    const int wid  = tid >> 5;
    const int b  = blockIdx.z;
    const int m0 = blockIdx.x * 128;
    const int n0 = blockIdx.y * 128;
    const int wm = (wid >> 2) * 64;
    const int wn = (wid & 3) * 32;

    const uint32_t sbase = smem_u32(smem);
    const __nv_bfloat16* Ab = A + (size_t)b * sAb + (size_t)m0 * ldA;
    const __nv_bfloat16* Bb = B + (size_t)b * sBb + (size_t)n0 * ldB;

    const int cr = tid >> 1;
    const int cs = tid & 1;

    float acc[4][4][4];
    #pragma unroll
    for (int i = 0; i < 4; i++)
        #pragma unroll
        for (int j = 0; j < 4; j++)
            #pragma unroll
            for (int e = 0; e < 4; e++) acc[i][j][e] = 0.f;

    const int nch = K / KCH;

    auto issue = [&](int ch, int buf) {
        const uint32_t sa  = sbase + buf * STAGEB + cr * ROWB;
        const uint32_t sbm = sa + TILEB;
        const __nv_bfloat16* ga = Ab + (size_t)cr * ldA + ch * KCH;
        const __nv_bfloat16* gb = Bb + (size_t)cr * ldB + ch * KCH;
        #pragma unroll
        for (int s = 0; s < 2; s++) {
            const int seg = cs + s * 2;
            CP_ASYNC16(sa + seg * 16, ga + seg * 8);
            CP_ASYNC16(sbm + seg * 16, gb + seg * 8);
        }
    };

    issue(0, 0);
    CP_COMMIT();

    for (int ch = 0; ch < nch; ch++) {
        if (ch + 1 < nch) { issue(ch + 1, (ch + 1) & 1); CP_COMMIT(); CP_WAIT1(); }
        else              { CP_WAIT0(); }
        __syncthreads();

        const uint32_t aT = sbase + (ch & 1) * STAGEB;
        const uint32_t bT = aT + TILEB;
        #pragma unroll
        for (int ks = 0; ks < 2; ks++) {
            uint32_t af[4][4], bfr[4][2];
            const int akoff = (ks * 16 + (lane >> 4) * 8) * 2;
            const int arow  = wm + (lane & 15);
            #pragma unroll
            for (int i = 0; i < 4; i++)
                LDSM_X4(af[i][0], af[i][1], af[i][2], af[i][3],
                        aT + (arow + i * 16) * ROWB + akoff);
            const int bkoff = (ks * 16 + ((lane >> 3) & 1) * 8) * 2;
            const int brow  = wn + (lane & 7);
            #pragma unroll
            for (int j = 0; j < 4; j++)
                LDSM_X2(bfr[j][0], bfr[j][1], bT + (brow + j * 8) * ROWB + bkoff);
            #pragma unroll
            for (int i = 0; i < 4; i++)
                #pragma unroll
                for (int j = 0; j < 4; j++)
                    MMA16816(acc[i][j], af[i], bfr[j]);
        }
        __syncthreads();
    }

    const int gid = lane >> 2, tig = lane & 3;
    if (mode == 0) {
        float* outb = outF + (size_t)b * sOb;
        #pragma unroll
        for (int i = 0; i < 4; i++) {
            #pragma unroll
            for (int j = 0; j < 4; j++) {
                const int r0 = m0 + wm + i * 16 + gid;
                const int c  = n0 + wn + j * 8 + tig * 2;
                *reinterpret_cast<float2*>(outb + (size_t)r0 * ldO + c) =
                    make_float2(acc[i][j][0], acc[i][j][1]);
                *reinterpret_cast<float2*>(outb + (size_t)(r0 + 8) * ldO + c) =
                    make_float2(acc[i][j][2], acc[i][j][3]);
            }
        }
    } else {
        // transposed bf16 store via smem: [128 c][136 m]
        __nv_bfloat16* smB = reinterpret_cast<__nv_bfloat16*>(smem);
        #pragma unroll
        for (int i = 0; i < 4; i++) {
            #pragma unroll
            for (int j = 0; j < 4; j++) {
                const int ml = wm + i * 16 + gid;
                const int cl = wn + j * 8 + tig * 2;
                smB[cl * OSTR + ml]           = __float2bfloat16(acc[i][j][0]);
                smB[(cl + 1) * OSTR + ml]     = __float2bfloat16(acc[i][j][1]);
                smB[cl * OSTR + ml + 8]       = __float2bfloat16(acc[i][j][2]);
                smB[(cl + 1) * OSTR + ml + 8] = __float2bfloat16(acc[i][j][3]);
            }
        }
        __syncthreads();
        __nv_bfloat16* og = outBT + (size_t)b * sOb;
        #pragma unroll
        for (int t = 0; t < 16; t++) {
            const int cl = wid + t * 8;
            const uint2 v = *reinterpret_cast<const uint2*>(&smB[cl * OSTR + lane * 4]);
            *reinterpret_cast<uint2*>(og + (size_t)(n0 + cl) * ldO + m0 + lane * 4) = v;
        }
    }
}

// ===========================================================================
// transpose + bf16 convert: out[b][n][k] = bf16(in[b][k][n]); 64k x 32n tiles
// ===========================================================================
__global__ void trans_kernel(const float* __restrict__ in, __nv_bfloat16* __restrict__ out, int K) {
    __shared__ float sm[64][33];
    const int b  = blockIdx.z;
    const int n0 = blockIdx.x * 32;
    const int k0 = blockIdx.y * 64;
    const int tx = threadIdx.x, ty = threadIdx.y;
    const float* ib = in + (size_t)b * K * NPIX;
    #pragma unroll
    for (int i = 0; i < 8; i++) {
        const int kk = ty + i * 8;
        sm[kk][tx] = ib[(size_t)(k0 + kk) * NPIX + n0 + tx];
    }
    __syncthreads();
    const int tid = ty * 32 + tx;
    const int n = tid >> 3, kg = tid & 7;
    __nv_bfloat16 v[8];
    #pragma unroll
    for (int j = 0; j < 8; j++) v[j] = __float2bfloat16(sm[kg * 8 + j][n]);
    __nv_bfloat16* ob = out + (size_t)b * NPIX * K;
    *reinterpret_cast<uint4*>(ob + (size_t)(n0 + n) * K + k0 + kg * 8) =
        *reinterpret_cast<const uint4*>(v);
}

__global__ void conv_bf16_kernel(const float* __restrict__ in, __nv_bfloat16* __restrict__ out, int n4) {
    const int i = blockIdx.x * blockDim.x + threadIdx.x;
    if (i < n4) {
        const float4 f = reinterpret_cast<const float4*>(in)[i];
        __nv_bfloat16 v[4] = {__float2bfloat16(f.x), __float2bfloat16(f.y),
                              __float2bfloat16(f.z), __float2bfloat16(f.w)};
        reinterpret_cast<uint2*>(out)[i] = *reinterpret_cast<const uint2*>(v);
    }
}

// ===========================================================================
// normalize q,k rows (C=256): 1 warp per row, float4 loads, uint4 bf16 stores
// ===========================================================================
__global__ void norm_kernel(const float* __restrict__ q, const float* __restrict__ k,
                            __nv_bfloat16* __restrict__ qb, __nv_bfloat16* __restrict__ kb) {
    const int lane = threadIdx.x & 31;
    const size_t row = (size_t)blockIdx.x * 8 + (threadIdx.x >> 5);
    const float4 q1 = *reinterpret_cast<const float4*>(q + row * CDIM + lane * 8);
    const float4 q2 = *reinterpret_cast<const float4*>(q + row * CDIM + lane * 8 + 4);
    const float4 k1 = *reinterpret_cast<const float4*>(k + row * CDIM + lane * 8);
    const float4 k2 = *reinterpret_cast<const float4*>(k + row * CDIM + lane * 8 + 4);
    float sq = q1.x*q1.x + q1.y*q1.y + q1.z*q1.z + q1.w*q1.w
             + q2.x*q2.x + q2.y*q2.y + q2.z*q2.z + q2.w*q2.w;
    float sk = k1.x*k1.x + k1.y*k1.y + k1.z*k1.z + k1.w*k1.w
             + k2.x*k2.x + k2.y*k2.y + k2.z*k2.z + k2.w*k2.w;
    #pragma unroll
    for (int o = 16; o > 0; o >>= 1) {
        sq += __shfl_xor_sync(0xffffffffu, sq, o);
        sk += __shfl_xor_sync(0xffffffffu, sk, o);
    }
    const float rq = 1.0f / fmaxf(sqrtf(sq), EPSN);
    const float rk = 1.0f / fmaxf(sqrtf(sk), EPSN);
    __nv_bfloat16 qv[8] = {
        __float2bfloat16(q1.x*rq), __float2bfloat16(q1.y*rq),
        __float2bfloat16(q1.z*rq), __float2bfloat16(q1.w*rq),
        __float2bfloat16(q2.x*rq), __float2bfloat16(q2.y*rq),
        __float2bfloat16(q2.z*rq), __float2bfloat16(q2.w*rq)};
    __nv_bfloat16 kv[8] = {
        __float2bfloat16(k1.x*rk), __float2bfloat16(k1.y*rk),
        __float2bfloat16(k1.z*rk), __float2bfloat16(k1.w*rk),
        __float2bfloat16(k2.x*rk), __float2bfloat16(k2.y*rk),
        __float2bfloat16(k2.z*rk), __float2bfloat16(k2.w*rk)};
    *reinterpret_cast<uint4*>(qb + row * CDIM + lane * 8) = *reinterpret_cast<const uint4*>(qv);
    *reinterpret_cast<uint4*>(kb + row * CDIM + lane * 8) = *reinterpret_cast<const uint4*>(kv);
}

// ===========================================================================
extern "C" void kernel_launch(void* const* d_in, const int* in_sizes, int n_in,
                              void* d_out, int out_size) {
    const float* x     = (const float*)d_in[0];
    const float* token = (const float*)d_in[1];
    const float* Wq    = (const float*)d_in[2];
    const float* Wk    = (const float*)d_in[3];
    const float* Wv    = (const float*)d_in[4];
    const float* alpha = (const float*)d_in[5];
    float* y = (float*)d_out;

    __nv_bfloat16 *xT, *tT, *Wqb, *Wkb, *Wvb, *qb, *kb, *vT;
    float *qf, *kf;
    cudaGetSymbolAddress((void**)&xT,  g_xT);
    cudaGetSymbolAddress((void**)&tT,  g_tT);
    cudaGetSymbolAddress((void**)&Wqb, g_Wqb);
    cudaGetSymbolAddress((void**)&Wkb, g_Wkb);
    cudaGetSymbolAddress((void**)&Wvb, g_Wvb);
    cudaGetSymbolAddress((void**)&qf,  g_qf);
    cudaGetSymbolAddress((void**)&kf,  g_kf);
    cudaGetSymbolAddress((void**)&qb,  g_qb);
    cudaGetSymbolAddress((void**)&kb,  g_kb);
    cudaGetSymbolAddress((void**)&vT,  g_vT);

    cudaFuncSetAttribute(attn_kernel, cudaFuncAttributeMaxDynamicSharedMemorySize, SM_TOT);

    // 1) weight converts + input transposes (fp32 -> bf16)
    conv_bf16_kernel<<<(CDIM * CDIM / 4 + 255) / 256, 256>>>(Wq, Wqb, CDIM * CDIM / 4);
    conv_bf16_kernel<<<(CDIM * TCDIM / 4 + 255) / 256, 256>>>(Wk, Wkb, CDIM * TCDIM / 4);
    conv_bf16_kernel<<<(CDIM * TCDIM / 4 + 255) / 256, 256>>>(Wv, Wvb, CDIM * TCDIM / 4);
    {
        dim3 b1(32, 8);
        dim3 g1(NPIX / 32, CDIM / 64, BATCH);
        trans_kernel<<<g1, b1>>>(x, xT, CDIM);
        dim3 g2(NPIX / 32, TCDIM / 64, BATCH);
        trans_kernel<<<g2, b1>>>(token, tT, TCDIM);
    }

    // 2) projections (HMMA); V writes vT bf16 transposed directly
    dim3 gp(NPIX / 128, CDIM / 128, BATCH);   // 18 x 2 x 8
    gemm_bf16_kernel<<<gp, 256>>>(xT, (size_t)NPIX * CDIM, CDIM,
                                  Wqb, 0, CDIM, CDIM, 0,
                                  qf, nullptr, (size_t)NPIX * CDIM, CDIM);
    gemm_bf16_kernel<<<gp, 256>>>(tT, (size_t)NPIX * TCDIM, TCDIM,
                                  Wkb, 0, TCDIM, TCDIM, 0,
                                  kf, nullptr, (size_t)NPIX * CDIM, CDIM);
    gemm_bf16_kernel<<<gp, 256>>>(tT, (size_t)NPIX * TCDIM, TCDIM,
                                  Wvb, 0, TCDIM, TCDIM, 1,
                                  nullptr, vT, (size_t)CDIM * NPIX, NPIX);

    // 3) normalize q,k -> bf16
    norm_kernel<<<BATCH * NPIX / 8, 256>>>(qf, kf, qb, kb);

    // 4) fused attention + residual -> y
    dim3 ga(NPIX / BR, BATCH);                // 18 x 8
    attn_kernel<<<ga, 256, SM_TOT>>>(qb, kb, vT, x, alpha, y);
}

// round 15
// speedup vs baseline: 9.2395x; 1.0015x over previous
#include <cuda_runtime.h>
#include <cuda_bf16.h>
#include <math.h>
#include <cstdint>

#define BATCH 8
#define CDIM  256
#define TCDIM 512
#define NPIX  2304          // 48*48
#define EPSN  1e-6f
#define SCALE 0.0625f       // 1/sqrt(256)

// ---------------- scratch (device globals: allocation-free) ----------------
__device__ __nv_bfloat16 g_xT [BATCH * NPIX * CDIM];        // x^T bf16 [B][N][256]
__device__ __nv_bfloat16 g_tT [BATCH * NPIX * TCDIM];       // token^T bf16 [B][N][512]
__device__ __nv_bfloat16 g_Wqb[CDIM * CDIM];
__device__ __nv_bfloat16 g_Wkb[CDIM * TCDIM];
__device__ __nv_bfloat16 g_Wvb[CDIM * TCDIM];
__device__ float         g_qf [BATCH * NPIX * CDIM];        // q fp32 [N][C]
__device__ float         g_kf [BATCH * NPIX * CDIM];        // k fp32 [N][C]
__device__ uint8_t       g_q8 [BATCH * NPIX * CDIM];        // normalized q e4m3
__device__ uint8_t       g_k8 [BATCH * NPIX * CDIM];        // normalized k e4m3
__device__ __nv_bfloat16 g_vT [BATCH * CDIM * NPIX];        // v^T bf16 [C][N]

// ======================= PTX helpers =======================================
__device__ __forceinline__ uint32_t smem_u32(const void* p) {
    uint32_t a;
    asm("{ .reg .u64 t; cvta.to.shared.u64 t, %1; cvt.u32.u64 %0, t; }" : "=r"(a) : "l"(p));
    return a;
}
__device__ __forceinline__ float ex2f(float x) {
    float y;
    asm("ex2.approx.f32 %0, %1;" : "=f"(y) : "f"(x));
    return y;
}
__device__ __forceinline__ uint32_t packbf(float lo, float hi) {
    __nv_bfloat162 h = __float22bfloat162_rn(make_float2(lo, hi));
    return *reinterpret_cast<uint32_t*>(&h);
}
// pack 4 floats -> 4 e4m3 bytes (byte0 = f0)
__device__ __forceinline__ uint32_t pack_e4m3_4(float f0, float f1, float f2, float f3) {
    uint32_t r;
    asm("{\n\t.reg .b16 l, h;\n\t"
        "cvt.rn.satfinite.e4m3x2.f32 l, %2, %1;\n\t"
        "cvt.rn.satfinite.e4m3x2.f32 h, %4, %3;\n\t"
        "mov.b32 %0, {l, h};\n\t}"
        : "=r"(r) : "f"(f0), "f"(f1), "f"(f2), "f"(f3));
    return r;
}
#define CP_ASYNC16(s, g) \
    asm volatile("cp.async.cg.shared.global [%0], [%1], 16;" :: "r"(s), "l"(g) : "memory")
#define CP_COMMIT()  asm volatile("cp.async.commit_group;" ::: "memory")
#define CP_WAIT1()   asm volatile("cp.async.wait_group 1;" ::: "memory")
#define CP_WAIT0()   asm volatile("cp.async.wait_group 0;" ::: "memory")
#define LDSM_X4(r0, r1, r2, r3, addr) \
    asm volatile("ldmatrix.sync.aligned.m8n8.x4.shared.b16 {%0,%1,%2,%3}, [%4];" \
        : "=r"(r0), "=r"(r1), "=r"(r2), "=r"(r3) : "r"(addr))
#define LDSM_X2(r0, r1, addr) \
    asm volatile("ldmatrix.sync.aligned.m8n8.x2.shared.b16 {%0,%1}, [%2];" \
        : "=r"(r0), "=r"(r1) : "r"(addr))
#define MMA16816(c, a, b) \
    asm volatile("mma.sync.aligned.m16n8k16.row.col.f32.bf16.bf16.f32 " \
        "{%0,%1,%2,%3}, {%4,%5,%6,%7}, {%8,%9}, {%0,%1,%2,%3};" \
        : "+f"((c)[0]), "+f"((c)[1]), "+f"((c)[2]), "+f"((c)[3]) \
        : "r"((a)[0]), "r"((a)[1]), "r"((a)[2]), "r"((a)[3]), "r"((b)[0]), "r"((b)[1]))
#define MMA16816R(c, a0, a1, a2, a3, b0, b1) \
    asm volatile("mma.sync.aligned.m16n8k16.row.col.f32.bf16.bf16.f32 " \
        "{%0,%1,%2,%3}, {%4,%5,%6,%7}, {%8,%9}, {%0,%1,%2,%3};" \
        : "+f"((c)[0]), "+f"((c)[1]), "+f"((c)[2]), "+f"((c)[3]) \
        : "r"(a0), "r"(a1), "r"(a2), "r"(a3), "r"(b0), "r"(b1))
#define MMAFP8(c, a0, a1, a2, a3, b0, b1) \
    asm volatile("mma.sync.aligned.m16n8k32.row.col.f32.e4m3.e4m3.f32 " \
        "{%0,%1,%2,%3}, {%4,%5,%6,%7}, {%8,%9}, {%0,%1,%2,%3};" \
        : "+f"((c)[0]), "+f"((c)[1]), "+f"((c)[2]), "+f"((c)[3]) \
        : "r"(a0), "r"(a1), "r"(a2), "r"(a3), "r"(b0), "r"(b1))

// ===========================================================================
// Fused attention + residual: per CTA 128 q rows, full D=256.
// S = q.k^T in FP8 (e4m3, m16n8k32); fixed-shift softmax; PV in bf16;
// epilogue: y = x + alpha * O^T (coalesced).
// ===========================================================================
#define BR    128
#define BC    64
#define NBLK  (NPIX / BC)                 // 36
#define QSTR8 272                         // 256 fp8 + 16B pad (phase 4 mod 32: conflict-free)
#define VSTR  144
#define SM_K0   (BR * QSTR8)              // 34816
#define SM_KB   (BC * QSTR8)              // 17408
#define SM_V0   (SM_K0 + 2 * SM_KB)       // 69632
#define SM_VB   (CDIM * VSTR)             // 36864
#define SM_TOT  (SM_V0 + 2 * SM_VB)       // 143360  (>= 256*136*4 = 139264 epilogue)
#define OSTR  136

__global__ void __launch_bounds__(256, 1)
attn_kernel(const uint8_t* __restrict__ q8,
            const uint8_t* __restrict__ k8,
            const __nv_bfloat16* __restrict__ vT,
            const float* __restrict__ x,
            const float* __restrict__ alpha,
            float* __restrict__ y)
{
    extern __shared__ __align__(128) unsigned char smem[];
    const uint32_t sb = smem_u32(smem);

    const int tid  = threadIdx.x;
    const int lane = tid & 31;
    const int wid  = tid >> 5;
    const int b    = blockIdx.y;
    const int m0   = blockIdx.x * BR;
    const int wrow = wid * 16;
    const int gid  = lane >> 2, tig = lane & 3;

    const uint8_t* qg = q8 + ((size_t)b * NPIX + m0) * CDIM;
    const uint8_t* kg = k8 + (size_t)b * NPIX * CDIM;
    const __nv_bfloat16* vg = vT + (size_t)b * CDIM * NPIX;
    const float av = *alpha;

    // ---- load q tile (once): 128 rows x 256B ----
    {
        const int row = tid >> 1, half = tid & 1;
        const uint32_t sq = sb + row * QSTR8;
        const uint8_t* gq = qg + (size_t)row * CDIM;
        #pragma unroll
        for (int s = 0; s < 8; s++) {
            const int seg = half + 2 * s;
            CP_ASYNC16(sq + seg * 16, gq + seg * 16);
        }
    }

    auto loadKV = [&](int j, int buf) {
        {   // k block: 64 rows x 256B fp8
            const int row = tid >> 2, q4 = tid & 3;
            const uint32_t sk = sb + SM_K0 + buf * SM_KB + row * QSTR8;
            const uint8_t* gk = kg + (size_t)(j * BC + row) * CDIM;
            #pragma unroll
            for (int s = 0; s < 4; s++) {
                const int seg = q4 + 4 * s;
                CP_ASYNC16(sk + seg * 16, gk + seg * 16);
            }
        }
        {   // v block: 256 c-rows x 128B bf16
            const uint32_t sv = sb + SM_V0 + buf * SM_VB + tid * VSTR;
            const __nv_bfloat16* gv = vg + (size_t)tid * NPIX + j * BC;
            #pragma unroll
            for (int s = 0; s < 8; s++)
                CP_ASYNC16(sv + s * 16, gv + s * 8);
        }
    };

    loadKV(0, 0);
    CP_COMMIT();
    CP_WAIT0();
    __syncthreads();

    float oacc[32][4];
    #pragma unroll
    for (int i = 0; i < 32; i++)
        #pragma unroll
        for (int e = 0; e < 4; e++) oacc[i][e] = 0.f;
    float l0 = 0.f, l1 = 0.f;

    const uint32_t sqa = sb + (wrow + (lane & 15)) * QSTR8 + (lane >> 4) * 16;
    const int x4row = (lane >> 4) * 8 + (lane & 7);
    const int x4off = ((lane >> 3) & 1) * 16;
    const float C1 = SCALE * 1.44269504f;
    const float C2 = SCALE * 1.44269504f;

    for (int j = 0; j < NBLK; j++) {
        if (j + 1 < NBLK) { loadKV(j + 1, (j + 1) & 1); CP_COMMIT(); }

        // ---- S = q . k^T  (fp8 e4m3, K=256 in 8 k32 chunks) ----
        float sacc[8][4];
        #pragma unroll
        for (int t = 0; t < 8; t++)
            #pragma unroll
            for (int e = 0; e < 4; e++) sacc[t][e] = 0.f;

        const uint32_t kba = sb + SM_K0 + (j & 1) * SM_KB + x4row * QSTR8 + x4off;
        #pragma unroll
        for (int kc = 0; kc < 8; kc++) {
            uint32_t a0, a1, a2, a3;
            LDSM_X4(a0, a1, a2, a3, sqa + kc * 32);
            #pragma unroll
            for (int np = 0; np < 4; np++) {
                uint32_t b0, b1, b2, b3;
                LDSM_X4(b0, b1, b2, b3, kba + np * 16 * QSTR8 + kc * 32);
                MMAFP8(sacc[2 * np],     a0, a1, a2, a3, b0, b1);
                MMAFP8(sacc[2 * np + 1], a0, a1, a2, a3, b2, b3);
            }
        }

        // ---- exp (fixed shift) + pack to bf16 ----
        uint32_t pf[8][2];
        #pragma unroll
        for (int t = 0; t < 8; t++) {
            const float e0 = ex2f(fmaf(sacc[t][0], C1, -C2));
            const float e1 = ex2f(fmaf(sacc[t][1], C1, -C2));
            const float e2 = ex2f(fmaf(sacc[t][2], C1, -C2));
            const float e3 = ex2f(fmaf(sacc[t][3], C1, -C2));
            l0 += e0 + e1;
            l1 += e2 + e3;
            pf[t][0] = packbf(e0, e1);
            pf[t][1] = packbf(e2, e3);
        }

        // ---- O += P . V  (bf16) ----
        const uint32_t vba4 = sb + SM_V0 + (j & 1) * SM_VB + x4row * VSTR + x4off;
        #pragma unroll
        for (int kk = 0; kk < 4; kk++) {
            const uint32_t a0 = pf[2 * kk][0], a1 = pf[2 * kk][1];
            const uint32_t a2 = pf[2 * kk + 1][0], a3 = pf[2 * kk + 1][1];
            #pragma unroll
            for (int np = 0; np < 16; np++) {
                uint32_t b0, b1, b2, b3;
                LDSM_X4(b0, b1, b2, b3, vba4 + np * 16 * VSTR + kk * 32);
                MMA16816R(oacc[2 * np],     a0, a1, a2, a3, b0, b1);
                MMA16816R(oacc[2 * np + 1], a0, a1, a2, a3, b2, b3);
            }
        }

        CP_WAIT0();
        __syncthreads();
    }

    // ---- normalize, stage O^T in smem ----
    l0 += __shfl_xor_sync(0xffffffffu, l0, 1);
    l0 += __shfl_xor_sync(0xffffffffu, l0, 2);
    l1 += __shfl_xor_sync(0xffffffffu, l1, 1);
    l1 += __shfl_xor_sync(0xffffffffu, l1, 2);
    const float inv0 = 1.0f / l0, inv1 = 1.0f / l1;

    float* smO = reinterpret_cast<float*>(smem);   // [256 c][136 n]
    const int rl = wrow + gid;
    #pragma unroll
    for (int nt = 0; nt < 32; nt++) {
        const int c = nt * 8 + tig * 2;
        smO[c * OSTR + rl]           = oacc[nt][0] * inv0;
        smO[(c + 1) * OSTR + rl]     = oacc[nt][1] * inv0;
        smO[c * OSTR + rl + 8]       = oacc[nt][2] * inv1;
        smO[(c + 1) * OSTR + rl + 8] = oacc[nt][3] * inv1;
    }
    __syncthreads();

    // ---- y = x + alpha * O^T ----
    const float* xg = x + (size_t)b * CDIM * NPIX + m0;
    float*       yg = y + (size_t)b * CDIM * NPIX + m0;
    #pragma unroll 4
    for (int t = 0; t < 32; t++) {
        const int cc = wid + t * 8;
        const float4 xv = *reinterpret_cast<const float4*>(xg + (size_t)cc * NPIX + lane * 4);
        const float4 ov = *reinterpret_cast<const float4*>(&smO[cc * OSTR + lane * 4]);
        float4 r;
        r.x = fmaf(av, ov.x, xv.x);
        r.y = fmaf(av, ov.y, xv.y);
        r.z = fmaf(av, ov.z, xv.z);
        r.w = fmaf(av, ov.w, xv.w);
        *reinterpret_cast<float4*>(yg + (size_t)cc * NPIX + lane * 4) = r;
    }
}

// ===========================================================================
// bf16 warp-MMA GEMM: D[128x128] = A(128,K) * B(128,K)^T.
// mode 0: fp32 out [m][n];  mode 1: bf16 transposed out [n][m] (via smem)
// ===========================================================================
#define KCH     32
#define ROWB    80
#define TILEB   (128 * ROWB)
#define STAGEB  (2 * TILEB)

__global__ void __launch_bounds__(256, 2)
gemm_bf16_kernel(const __nv_bfloat16* __restrict__ A, size_t sAb, int ldA,
                 const __nv_bfloat16* __restrict__ B, size_t sBb, int ldB,
                 int K, int mode,
                 float* __restrict__ outF, __nv_bfloat16* __restrict__ outBT,
                 size_t sOb, int ldO)
{
    __shared__ __align__(128) unsigned char smem[2 * STAGEB];

    const int tid  = threadIdx.x;
    const int lane = tid & 31;
    const int wid  = tid >> 5;
    const int b  = blockIdx.z;
    const int m0 = blockIdx.x * 128;
    const int n0 = blockIdx.y * 128;
    const int wm = (wid >> 2) * 64;
    const int wn = (wid & 3) * 32;

    const uint32_t sbase = smem_u32(smem);
    const __nv_bfloat16* Ab = A + (size_t)b * sAb + (size_t)m0 * ldA;
    const __nv_bfloat16* Bb = B + (size_t)b * sBb + (size_t)n0 * ldB;

    const int cr = tid >> 1;
    const int cs = tid & 1;

    float acc[4][4][4];
    #pragma unroll
    for (int i = 0; i < 4; i++)
        #pragma unroll
        for (int j = 0; j < 4; j++)
            #pragma unroll
            for (int e = 0; e < 4; e++) acc[i][j][e] = 0.f;

    const int nch = K / KCH;

    auto issue = [&](int ch, int buf) {
        const uint32_t sa  = sbase + buf * STAGEB + cr * ROWB;
        const uint32_t sbm = sa + TILEB;
        const __nv_bfloat16* ga = Ab + (size_t)cr * ldA + ch * KCH;
        const __nv_bfloat16* gb = Bb + (size_t)cr * ldB + ch * KCH;
        #pragma unroll
        for (int s = 0; s < 2; s++) {
            const int seg = cs + s * 2;
            CP_ASYNC16(sa + seg * 16, ga + seg * 8);
            CP_ASYNC16(sbm + seg * 16, gb + seg * 8);
        }
    };

    issue(0, 0);
    CP_COMMIT();

    for (int ch = 0; ch < nch; ch++) {
        if (ch + 1 < nch) { issue(ch + 1, (ch + 1) & 1); CP_COMMIT(); CP_WAIT1(); }
        else              { CP_WAIT0(); }
        __syncthreads();

        const uint32_t aT = sbase + (ch & 1) * STAGEB;
        const uint32_t bT = aT + TILEB;
        #pragma unroll
        for (int ks = 0; ks < 2; ks++) {
            uint32_t af[4][4], bfr[4][2];
            const int akoff = (ks * 16 + (lane >> 4) * 8) * 2;
            const int arow  = wm + (lane & 15);
            #pragma unroll
            for (int i = 0; i < 4; i++)
                LDSM_X4(af[i][0], af[i][1], af[i][2], af[i][3],
                        aT + (arow + i * 16) * ROWB + akoff);
            const int bkoff = (ks * 16 + ((lane >> 3) & 1) * 8) * 2;
            const int brow  = wn + (lane & 7);
            #pragma unroll
            for (int j = 0; j < 4; j++)
                LDSM_X2(bfr[j][0], bfr[j][1], bT + (brow + j * 8) * ROWB + bkoff);
            #pragma unroll
            for (int i = 0; i < 4; i++)
                #pragma unroll
                for (int j = 0; j < 4; j++)
                    MMA16816(acc[i][j], af[i], bfr[j]);
        }
        __syncthreads();
    }

    const int gid = lane >> 2, tig = lane & 3;
    if (mode == 0) {
        float* outb = outF + (size_t)b * sOb;
        #pragma unroll
        for (int i = 0; i < 4; i++) {
            #pragma unroll
            for (int j = 0; j < 4; j++) {
                const int r0 = m0 + wm + i * 16 + gid;
                const int c  = n0 + wn + j * 8 + tig * 2;
                *reinterpret_cast<float2*>(outb + (size_t)r0 * ldO + c) =
                    make_float2(acc[i][j][0], acc[i][j][1]);
                *reinterpret_cast<float2*>(outb + (size_t)(r0 + 8) * ldO + c) =
                    make_float2(acc[i][j][2], acc[i][j][3]);
            }
        }
    } else {
        __nv_bfloat16* smB = reinterpret_cast<__nv_bfloat16*>(smem);
        #pragma unroll
        for (int i = 0; i < 4; i++) {
            #pragma unroll
            for (int j = 0; j < 4; j++) {
                const int ml = wm + i * 16 + gid;
                const int cl = wn + j * 8 + tig * 2;
                smB[cl * OSTR + ml]           = __float2bfloat16(acc[i][j][0]);
                smB[(cl + 1) * OSTR + ml]     = __float2bfloat16(acc[i][j][1]);
                smB[cl * OSTR + ml + 8]       = __float2bfloat16(acc[i][j][2]);
                smB[(cl + 1) * OSTR + ml + 8] = __float2bfloat16(acc[i][j][3]);
            }
        }
        __syncthreads();
        __nv_bfloat16* og = outBT + (size_t)b * sOb;
        #pragma unroll
        for (int t = 0; t < 16; t++) {
            const int cl = wid + t * 8;
            const uint2 v = *reinterpret_cast<const uint2*>(&smB[cl * OSTR + lane * 4]);
            *reinterpret_cast<uint2*>(og + (size_t)(n0 + cl) * ldO + m0 + lane * 4) = v;
        }
    }
}

// ===========================================================================
// merged transpose + bf16 convert for x (K=256) and token (K=512)
// ===========================================================================
__global__ void trans2_kernel(const float* __restrict__ x, const float* __restrict__ token,
                              __nv_bfloat16* __restrict__ xT, __nv_bfloat16* __restrict__ tT) {
    __shared__ float sm[64][33];
    const int b  = blockIdx.z;
    const bool isX = blockIdx.y < (CDIM / 64);
    const int K  = isX ? CDIM : TCDIM;
    const int k0 = (isX ? blockIdx.y : blockIdx.y - CDIM / 64) * 64;
    const float* in = isX ? x : token;
    __nv_bfloat16* out = isX ? xT : tT;
    const int n0 = blockIdx.x * 32;
    const int tx = threadIdx.x, ty = threadIdx.y;
    const float* ib = in + (size_t)b * K * NPIX;
    #pragma unroll
    for (int i = 0; i < 8; i++) {
        const int kk = ty + i * 8;
        sm[kk][tx] = ib[(size_t)(k0 + kk) * NPIX + n0 + tx];
    }
    __syncthreads();
    const int tid = ty * 32 + tx;
    const int n = tid >> 3, kg = tid & 7;
    __nv_bfloat16 v[8];
    #pragma unroll
    for (int j = 0; j < 8; j++) v[j] = __float2bfloat16(sm[kg * 8 + j][n]);
    __nv_bfloat16* ob = out + (size_t)b * NPIX * K;
    *reinterpret_cast<uint4*>(ob + (size_t)(n0 + n) * K + k0 + kg * 8) =
        *reinterpret_cast<const uint4*>(v);
}

// merged 3-weight fp32->bf16 convert
__global__ void conv3_kernel(const float* __restrict__ Wq, const float* __restrict__ Wk,
                             const float* __restrict__ Wv,
                             __nv_bfloat16* __restrict__ Wqb, __nv_bfloat16* __restrict__ Wkb,
                             __nv_bfloat16* __restrict__ Wvb) {
    const int i = blockIdx.x * blockDim.x + threadIdx.x;
    const int NQ = CDIM * CDIM / 4, NK = CDIM * TCDIM / 4;
    const float* in;
    __nv_bfloat16* out;
    int idx;
    if (i < NQ)           { in = Wq; out = Wqb; idx = i; }
    else if (i < NQ + NK) { in = Wk; out = Wkb; idx = i - NQ; }
    else if (i < NQ + 2 * NK) { in = Wv; out = Wvb; idx = i - NQ - NK; }
    else return;
    const float4 f = reinterpret_cast<const float4*>(in)[idx];
    __nv_bfloat16 v[4] = {__float2bfloat16(f.x), __float2bfloat16(f.y),
                          __float2bfloat16(f.z), __float2bfloat16(f.w)};
    reinterpret_cast<uint2*>(out)[idx] = *reinterpret_cast<const uint2*>(v);
}

// ===========================================================================
// normalize q,k rows (C=256) -> e4m3; 1 warp per row
// ===========================================================================
__global__ void norm_kernel(const float* __restrict__ q, const float* __restrict__ k,
                            uint8_t* __restrict__ q8, uint8_t* __restrict__ k8) {
    const int lane = threadIdx.x & 31;
    const size_t row = (size_t)blockIdx.x * 8 + (threadIdx.x >> 5);
    const float4 q1 = *reinterpret_cast<const float4*>(q + row * CDIM + lane * 8);
    const float4 q2 = *reinterpret_cast<const float4*>(q + row * CDIM + lane * 8 + 4);
    const float4 k1 = *reinterpret_cast<const float4*>(k + row * CDIM + lane * 8);
    const float4 k2 = *reinterpret_cast<const float4*>(k + row * CDIM + lane * 8 + 4);
    float sq = q1.x*q1.x + q1.y*q1.y + q1.z*q1.z + q1.w*q1.w
             + q2.x*q2.x + q2.y*q2.y + q2.z*q2.z + q2.w*q2.w;
    float sk = k1.x*k1.x + k1.y*k1.y + k1.z*k1.z + k1.w*k1.w
             + k2.x*k2.x + k2.y*k2.y + k2.z*k2.z + k2.w*k2.w;
    #pragma unroll
    for (int o = 16; o > 0; o >>= 1) {
        sq += __shfl_xor_sync(0xffffffffu, sq, o);
        sk += __shfl_xor_sync(0xffffffffu, sk, o);
    }
    const float rq = 1.0f / fmaxf(sqrtf(sq), EPSN);
    const float rk = 1.0f / fmaxf(sqrtf(sk), EPSN);
    uint2 qp, kp;
    qp.x = pack_e4m3_4(q1.x*rq, q1.y*rq, q1.z*rq, q1.w*rq);
    qp.y = pack_e4m3_4(q2.x*rq, q2.y*rq, q2.z*rq, q2.w*rq);
    kp.x = pack_e4m3_4(k1.x*rk, k1.y*rk, k1.z*rk, k1.w*rk);
    kp.y = pack_e4m3_4(k2.x*rk, k2.y*rk, k2.z*rk, k2.w*rk);
    *reinterpret_cast<uint2*>(q8 + row * CDIM + lane * 8) = qp;
    *reinterpret_cast<uint2*>(k8 + row * CDIM + lane * 8) = kp;
}

// ===========================================================================
extern "C" void kernel_launch(void* const* d_in, const int* in_sizes, int n_in,
                              void* d_out, int out_size) {
    const float* x     = (const float*)d_in[0];
    const float* token = (const float*)d_in[1];
    const float* Wq    = (const float*)d_in[2];
    const float* Wk    = (const float*)d_in[3];
    const float* Wv    = (const float*)d_in[4];
    const float* alpha = (const float*)d_in[5];
    float* y = (float*)d_out;

    __nv_bfloat16 *xT, *tT, *Wqb, *Wkb, *Wvb, *vT;
    uint8_t *q8, *k8;
    float *qf, *kf;
    cudaGetSymbolAddress((void**)&xT,  g_xT);
    cudaGetSymbolAddress((void**)&tT,  g_tT);
    cudaGetSymbolAddress((void**)&Wqb, g_Wqb);
    cudaGetSymbolAddress((void**)&Wkb, g_Wkb);
    cudaGetSymbolAddress((void**)&Wvb, g_Wvb);
    cudaGetSymbolAddress((void**)&qf,  g_qf);
    cudaGetSymbolAddress((void**)&kf,  g_kf);
    cudaGetSymbolAddress((void**)&q8,  g_q8);
    cudaGetSymbolAddress((void**)&k8,  g_k8);
    cudaGetSymbolAddress((void**)&vT,  g_vT);

    cudaFuncSetAttribute(attn_kernel, cudaFuncAttributeMaxDynamicSharedMemorySize, SM_TOT);

    // 1) weight converts + input transposes (merged launches)
    {
        const int total = CDIM * CDIM / 4 + 2 * (CDIM * TCDIM / 4);
        conv3_kernel<<<(total + 255) / 256, 256>>>(Wq, Wk, Wv, Wqb, Wkb, Wvb);
        dim3 b1(32, 8);
        dim3 gt(NPIX / 32, CDIM / 64 + TCDIM / 64, BATCH);  // 72 x 12 x 8
        trans2_kernel<<<gt, b1>>>(x, token, xT, tT);
    }

    // 2) projections (HMMA); V writes vT bf16 transposed directly
    dim3 gp(NPIX / 128, CDIM / 128, BATCH);   // 18 x 2 x 8
    gemm_bf16_kernel<<<gp, 256>>>(xT, (size_t)NPIX * CDIM, CDIM,
                                  Wqb, 0, CDIM, CDIM, 0,
                                  qf, nullptr, (size_t)NPIX * CDIM, CDIM);
    gemm_bf16_kernel<<<gp, 256>>>(tT, (size_t)NPIX * TCDIM, TCDIM,
                                  Wkb, 0, TCDIM, TCDIM, 0,
                                  kf, nullptr, (size_t)NPIX * CDIM, CDIM);
    gemm_bf16_kernel<<<gp, 256>>>(tT, (size_t)NPIX * TCDIM, TCDIM,
                                  Wvb, 0, TCDIM, TCDIM, 1,
                                  nullptr, vT, (size_t)CDIM * NPIX, NPIX);

    // 3) normalize q,k -> e4m3
    norm_kernel<<<BATCH * NPIX / 8, 256>>>(qf, kf, q8, k8);

    // 4) fused attention (fp8 S, bf16 PV) + residual -> y
    dim3 ga(NPIX / BR, BATCH);                // 18 x 8
    attn_kernel<<<ga, 256, SM_TOT>>>(q8, k8, vT, x, alpha, y);
}